// round 14
// baseline (speedup 1.0000x reference)
#include <cuda_runtime.h>
#include <cuda_bf16.h>
#include <math.h>
#include <stdint.h>

// ---------------- problem constants ----------------
#define NVB   6
#define VV    3
#define BB    2
#define CC    256
#define LTOK  1024
#define TKX   2048
#define NH    4
#define HD    64
#define FFNI  512
#define FFNH  2048

#define ROWS_ (NVB*LTOK)          // 6144
#define XW    (NVB*LTOK*CC/2)
#define NAPP  (NVB*LTOK*NH*16)    // 393216

// ---------------- device scratch ----------------
__device__ float g_x   [ROWS_*CC];
__device__ float g_qkv [ROWS_*768];
__device__ uint32_t g_qph[NVB*NH*LTOK*32], g_qpl[NVB*NH*LTOK*32];
__device__ uint32_t g_kph[NVB*NH*TKX*HD/2], g_kpl[NVB*NH*TKX*HD/2];
__device__ uint32_t g_vph[NVB*NH*TKX*HD/2], g_vpl[NVB*NH*TKX*HD/2];  // V^T packed
__device__ float g_msg [ROWS_*CC];
__device__ float g_msg2[2*ROWS_*CC];          // split-K partials (msg)
__device__ float g_h22 [4*ROWS_*CC];          // split-K partials (W2, x4)
__device__ float g_Mq  [NVB*LTOK*16];
__device__ float g_Mqi [NVB*LTOK*16];
__device__ float g_Mkv [NVB*TKX*16];

__device__ uint32_t g_xh   [XW],  g_xl   [XW];
__device__ uint32_t g_xpreh[XW],  g_xprel[XW];
__device__ uint32_t g_omh  [XW],  g_oml  [XW];
__device__ uint32_t g_cath [ROWS_*FFNI/2], g_catl[ROWS_*FFNI/2];
__device__ uint32_t g_hh   [ROWS_*FFNH/2], g_hl  [ROWS_*FFNH/2];
#define WQKV0 0
#define WMO   393216
#define W1O   524288
#define W2O   1572864
#define WTOT  2097152
__device__ uint32_t g_wh[WTOT], g_wl[WTOT];

// ---------------- helpers ----------------
__device__ __forceinline__ void cvt_hl(float x, float y, uint32_t& hi, uint32_t& lo) {
    __nv_bfloat162 h = __floats2bfloat162_rn(x, y);
    float rx = x - __bfloat162float(h.x);
    float ry = y - __bfloat162float(h.y);
    __nv_bfloat162 l = __floats2bfloat162_rn(rx, ry);
    hi = *reinterpret_cast<uint32_t*>(&h);
    lo = *reinterpret_cast<uint32_t*>(&l);
}

__device__ __forceinline__ void mma_bf16(float* c, const uint32_t* a, const uint32_t* b) {
    asm volatile(
        "mma.sync.aligned.m16n8k16.row.col.f32.bf16.bf16.f32 "
        "{%0,%1,%2,%3}, {%4,%5,%6,%7}, {%8,%9}, {%0,%1,%2,%3};"
        : "+f"(c[0]), "+f"(c[1]), "+f"(c[2]), "+f"(c[3])
        : "r"(a[0]), "r"(a[1]), "r"(a[2]), "r"(a[3]), "r"(b[0]), "r"(b[1]));
}

__device__ __forceinline__ void ldsm4(uint32_t* r, uint32_t addr) {
    asm volatile("ldmatrix.sync.aligned.m8n8.x4.shared.b16 {%0,%1,%2,%3}, [%4];"
        : "=r"(r[0]), "=r"(r[1]), "=r"(r[2]), "=r"(r[3]) : "r"(addr));
}

__device__ __forceinline__ uint32_t smem_u32(const void* p) {
    uint32_t a;
    asm("{ .reg .u64 t; cvta.to.shared.u64 t, %1; cvt.u32.u64 %0, t; }" : "=r"(a) : "l"(p));
    return a;
}

__device__ __forceinline__ void cp16(uint32_t smem, const void* g) {
    asm volatile("cp.async.cg.shared.global [%0], [%1], 16;" :: "r"(smem), "l"(g));
}
#define CP_COMMIT() asm volatile("cp.async.commit_group;")
#define CP_WAIT(N)  asm volatile("cp.async.wait_group %0;" :: "n"(N))

// ---------------- all-weight conversion + QKV repack ----------------
__global__ void k_cvt_all(const float* __restrict__ Wq, const float* __restrict__ Wk,
                          const float* __restrict__ Wv, const float* __restrict__ Wm,
                          const float* __restrict__ W1, const float* __restrict__ W2,
                          uint32_t* __restrict__ wh, uint32_t* __restrict__ wl) {
    int i = blockIdx.x * blockDim.x + threadIdx.x;
    if (i >= WTOT) return;
    const float* src;
    if (i < WMO) {
        int lyp  = i / 98304;
        int sub  = i % 98304;
        int which = sub / 32768;
        int woff  = sub % 32768;
        const float* base = (which == 0) ? Wq : (which == 1) ? Wk : Wv;
        src = base + (size_t)lyp * 65536 + (size_t)woff * 2;
    } else if (i < W1O) {
        src = Wm + (size_t)(i - WMO) * 2;
    } else if (i < W2O) {
        src = W1 + (size_t)(i - W1O) * 2;
    } else {
        src = W2 + (size_t)(i - W2O) * 2;
    }
    float2 v = *reinterpret_cast<const float2*>(src);
    uint32_t h, l;
    cvt_hl(v.x, v.y, h, l);
    wh[i] = h; wl[i] = l;
}

// ---------------- tensor-core bf16x3 GEMM (BN template, split-K via z) -------
template<int BN, int OUT>
__global__ __launch_bounds__(256)
void tc_gemm(const uint32_t* __restrict__ Ah, const uint32_t* __restrict__ Al,
             const uint32_t* __restrict__ A2h, const uint32_t* __restrict__ A2l,
             int nsplit,
             const uint32_t* __restrict__ Bh, const uint32_t* __restrict__ Bl,
             float* __restrict__ C, uint32_t* __restrict__ Oh, uint32_t* __restrict__ Ol,
             int M, int N, int K, int Krow)
{
    constexpr int WARPS_N = BN / 32;
    constexpr int WMX = 128 / (8 / WARPS_N);
    constexpr int MT = WMX / 16;
    constexpr int B_HI = BN * 48;
    constexpr int STAGE = 12288 + 2 * B_HI;

    extern __shared__ uint32_t smem[];
    const uint32_t sb0 = smem_u32(smem);

    const int m0 = blockIdx.y * 128;
    const int n0 = blockIdx.x * BN;
    const int kz = blockIdx.z;
    const int tid = threadIdx.x;
    const int wid = tid >> 5, lane = tid & 31;
    const int g = lane >> 2, tg = lane & 3;
    const int warp_m = wid / WARPS_N, warp_n = wid % WARPS_N;
    const int wm0 = warp_m * WMX, wn0 = warp_n * 32;
    const int Krow2 = Krow >> 1;
    const size_t kzoff = (size_t)kz * (K >> 1);

    const int rowa = tid >> 1, hw = (tid & 1) * 4;

    const int a_lrow = lane & 15;
    const int a_lcol = (lane >> 4) * 4;
    const int b_lrow = (lane & 7) + ((lane >> 4) << 3);
    const int b_lcol = ((lane >> 3) & 1) * 4;

    float acc[MT][4][4];
    #pragma unroll
    for (int i = 0; i < MT; i++)
        #pragma unroll
        for (int j = 0; j < 4; j++)
            #pragma unroll
            for (int r = 0; r < 4; r++) acc[i][j][r] = 0.f;

    const bool useA2 = (n0 >= nsplit);
    const uint32_t* Ab  = (useA2 ? A2h : Ah) + (size_t)(m0 + rowa) * Krow2 + hw + kzoff;
    const uint32_t* Alb = (useA2 ? A2l : Al) + (size_t)(m0 + rowa) * Krow2 + hw + kzoff;
    const uint32_t* Bb  = Bh + (size_t)(n0 + rowa) * Krow2 + hw + kzoff;
    const uint32_t* Blb = Bl + (size_t)(n0 + rowa) * Krow2 + hw + kzoff;
    C += (size_t)kz * M * N;

    const uint32_t dst_off = (uint32_t)(rowa * 12 + hw) * 4;
    const int nk = K >> 4;

    #define ISSUE(tile, stage) do {                                   \
        uint32_t sb = sb0 + (stage) * (uint32_t)STAGE;                \
        int ko = (tile) * 8;                                          \
        cp16(sb + dst_off,        Ab + ko);                           \
        cp16(sb + 6144 + dst_off, Alb + ko);                          \
        if (BN == 128 || tid < 128) {                                 \
            cp16(sb + 12288 + dst_off,        Bb + ko);               \
            cp16(sb + 12288 + B_HI + dst_off, Blb + ko);              \
        }                                                             \
    } while (0)

    #pragma unroll
    for (int s = 0; s < 3; s++) {
        if (s < nk) ISSUE(s, s);
        CP_COMMIT();
    }

    for (int kt = 0; kt < nk; kt++) {
        if (kt + 3 < nk) ISSUE(kt + 3, (kt + 3) & 3);
        CP_COMMIT();
        CP_WAIT(3);
        __syncthreads();

        const uint32_t sb = sb0 + (kt & 3) * (uint32_t)STAGE;
        uint32_t ah[MT][4], al[MT][4], bh2[4][2], bl2[4][2];
        #pragma unroll
        for (int mi = 0; mi < MT; mi++) {
            uint32_t woff = (uint32_t)((wm0 + mi*16 + a_lrow) * 12 + a_lcol) * 4;
            ldsm4(ah[mi], sb + woff);
            ldsm4(al[mi], sb + 6144 + woff);
        }
        #pragma unroll
        for (int p = 0; p < 2; p++) {
            uint32_t woff = (uint32_t)((wn0 + p*16 + b_lrow) * 12 + b_lcol) * 4;
            uint32_t r[4];
            ldsm4(r, sb + 12288 + woff);
            bh2[2*p][0] = r[0]; bh2[2*p][1] = r[1];
            bh2[2*p+1][0] = r[2]; bh2[2*p+1][1] = r[3];
            ldsm4(r, sb + 12288 + B_HI + woff);
            bl2[2*p][0] = r[0]; bl2[2*p][1] = r[1];
            bl2[2*p+1][0] = r[2]; bl2[2*p+1][1] = r[3];
        }
        #pragma unroll
        for (int mi = 0; mi < MT; mi++)
            #pragma unroll
            for (int ni = 0; ni < 4; ni++) {
                mma_bf16(acc[mi][ni], ah[mi], bh2[ni]);
                mma_bf16(acc[mi][ni], ah[mi], bl2[ni]);
                mma_bf16(acc[mi][ni], al[mi], bh2[ni]);
            }
        __syncthreads();
    }
    #undef ISSUE

    #pragma unroll
    for (int mi = 0; mi < MT; mi++) {
        #pragma unroll
        for (int ni = 0; ni < 4; ni++) {
            long long row0 = m0 + wm0 + mi * 16 + g;
            int col = n0 + wn0 + ni * 8 + tg * 2;
            if (OUT == 0) {
                *reinterpret_cast<float2*>(&C[row0 * N + col]) =
                    make_float2(acc[mi][ni][0], acc[mi][ni][1]);
                *reinterpret_cast<float2*>(&C[(row0 + 8) * N + col]) =
                    make_float2(acc[mi][ni][2], acc[mi][ni][3]);
            } else {
                float r[4];
                #pragma unroll
                for (int t = 0; t < 4; t++) {
                    float v = acc[mi][ni][t];
                    r[t] = 0.5f * v * (1.0f + erff(v * 0.70710678118654752f));
                }
                uint32_t h0, l0, h1, l1;
                cvt_hl(r[0], r[1], h0, l0);
                cvt_hl(r[2], r[3], h1, l1);
                size_t w0 = (size_t)(row0 * N + col) >> 1;
                size_t w1 = (size_t)((row0 + 8) * N + col) >> 1;
                Oh[w0] = h0; Ol[w0] = l0;
                Oh[w1] = h1; Ol[w1] = l1;
            }
        }
    }
}

// ---------------- fused flash attention + output apply ----------------
// Q packed hi/lo [nh][LTOK][32w], K packed [nh][Tk][32w], V^T packed.
// Epilogue applies per-token Mqi and writes om hi/lo directly (replaces k_apply_out).
#define FA_SK 36
__global__ __launch_bounds__(256)
void k_flash(const uint32_t* __restrict__ qph, const uint32_t* __restrict__ qpl,
             const uint32_t* __restrict__ kph, const uint32_t* __restrict__ kpl,
             const uint32_t* __restrict__ vph, const uint32_t* __restrict__ vpl,
             const float* __restrict__ Mqi,
             uint32_t* __restrict__ omh, uint32_t* __restrict__ oml, int Tk)
{
    __shared__ uint32_t khw[64*FA_SK], klw[64*FA_SK];
    __shared__ uint32_t vhw[64*FA_SK], vlw[64*FA_SK];

    const int nh = blockIdx.y;
    const int q0 = blockIdx.x * 128;
    const int tid = threadIdx.x, wid = tid >> 5, lane = tid & 31;
    const int g = lane >> 2, tg = lane & 3;

    const uint32_t* Qh = qph + ((size_t)nh * LTOK + q0) * 32;
    const uint32_t* Ql = qpl + ((size_t)nh * LTOK + q0) * 32;
    const uint32_t* Kh = kph + (size_t)nh * Tk * 32;
    const uint32_t* Kl = kpl + (size_t)nh * Tk * 32;
    const uint32_t* Vh = vph + (size_t)nh * HD * (Tk >> 1);
    const uint32_t* Vl = vpl + (size_t)nh * HD * (Tk >> 1);

    const int row0 = wid * 16 + g;
    uint32_t qh[4][4], ql[4][4];
    #pragma unroll
    for (int kk = 0; kk < 4; kk++) {
        int w0 = row0 * 32 + kk * 8 + tg;
        int w1 = (row0 + 8) * 32 + kk * 8 + tg;
        qh[kk][0] = Qh[w0];     ql[kk][0] = Ql[w0];
        qh[kk][1] = Qh[w1];     ql[kk][1] = Ql[w1];
        qh[kk][2] = Qh[w0 + 4]; ql[kk][2] = Ql[w0 + 4];
        qh[kk][3] = Qh[w1 + 4]; ql[kk][3] = Ql[w1 + 4];
    }

    float m0 = -1e30f, m1 = -1e30f, l0 = 0.f, l1 = 0.f;
    float oacc[8][4];
    #pragma unroll
    for (int i = 0; i < 8; i++)
        #pragma unroll
        for (int t = 0; t < 4; t++) oacc[i][t] = 0.f;

    const int r = tid >> 2, c2 = (tid & 3) * 8;
    uint4 kh0, kh1, kl0, kl1, vh0, vh1, vl0, vl1;
    {
        const uint32_t* sk = Kh + (size_t)r * 32 + c2;
        const uint32_t* sl = Kl + (size_t)r * 32 + c2;
        const uint32_t* tv = Vh + (size_t)r * (Tk >> 1) + c2;
        const uint32_t* tl = Vl + (size_t)r * (Tk >> 1) + c2;
        kh0 = *reinterpret_cast<const uint4*>(sk);
        kh1 = *reinterpret_cast<const uint4*>(sk + 4);
        kl0 = *reinterpret_cast<const uint4*>(sl);
        kl1 = *reinterpret_cast<const uint4*>(sl + 4);
        vh0 = *reinterpret_cast<const uint4*>(tv);
        vh1 = *reinterpret_cast<const uint4*>(tv + 4);
        vl0 = *reinterpret_cast<const uint4*>(tl);
        vl1 = *reinterpret_cast<const uint4*>(tl + 4);
    }

    for (int kv0 = 0; kv0 < Tk; kv0 += 64) {
        {
            int w = r * FA_SK + c2;
            *reinterpret_cast<uint4*>(&khw[w]) = kh0;
            *reinterpret_cast<uint4*>(&khw[w + 4]) = kh1;
            *reinterpret_cast<uint4*>(&klw[w]) = kl0;
            *reinterpret_cast<uint4*>(&klw[w + 4]) = kl1;
            *reinterpret_cast<uint4*>(&vhw[w]) = vh0;
            *reinterpret_cast<uint4*>(&vhw[w + 4]) = vh1;
            *reinterpret_cast<uint4*>(&vlw[w]) = vl0;
            *reinterpret_cast<uint4*>(&vlw[w + 4]) = vl1;
        }
        __syncthreads();

        if (kv0 + 64 < Tk) {
            const uint32_t* sk = Kh + (size_t)(kv0 + 64 + r) * 32 + c2;
            const uint32_t* sl = Kl + (size_t)(kv0 + 64 + r) * 32 + c2;
            const uint32_t* tv = Vh + (size_t)r * (Tk >> 1) + ((kv0 + 64) >> 1) + c2;
            const uint32_t* tl = Vl + (size_t)r * (Tk >> 1) + ((kv0 + 64) >> 1) + c2;
            kh0 = *reinterpret_cast<const uint4*>(sk);
            kh1 = *reinterpret_cast<const uint4*>(sk + 4);
            kl0 = *reinterpret_cast<const uint4*>(sl);
            kl1 = *reinterpret_cast<const uint4*>(sl + 4);
            vh0 = *reinterpret_cast<const uint4*>(tv);
            vh1 = *reinterpret_cast<const uint4*>(tv + 4);
            vl0 = *reinterpret_cast<const uint4*>(tl);
            vl1 = *reinterpret_cast<const uint4*>(tl + 4);
        }

        float sacc[8][4];
        #pragma unroll
        for (int i = 0; i < 8; i++)
            #pragma unroll
            for (int t = 0; t < 4; t++) sacc[i][t] = 0.f;
        #pragma unroll
        for (int kk = 0; kk < 4; kk++) {
            #pragma unroll
            for (int ni = 0; ni < 8; ni++) {
                uint32_t bh[2], bl[2];
                int off = (ni * 8 + g) * FA_SK + kk * 8 + tg;
                bh[0] = khw[off]; bh[1] = khw[off + 4];
                bl[0] = klw[off]; bl[1] = klw[off + 4];
                mma_bf16(sacc[ni], qh[kk], bh);
                mma_bf16(sacc[ni], qh[kk], bl);
                mma_bf16(sacc[ni], ql[kk], bh);
            }
        }

        float mx0 = -1e30f, mx1 = -1e30f;
        #pragma unroll
        for (int ni = 0; ni < 8; ni++) {
            mx0 = fmaxf(mx0, fmaxf(sacc[ni][0], sacc[ni][1]));
            mx1 = fmaxf(mx1, fmaxf(sacc[ni][2], sacc[ni][3]));
        }
        mx0 = fmaxf(mx0, __shfl_xor_sync(0xffffffff, mx0, 1));
        mx0 = fmaxf(mx0, __shfl_xor_sync(0xffffffff, mx0, 2));
        mx1 = fmaxf(mx1, __shfl_xor_sync(0xffffffff, mx1, 1));
        mx1 = fmaxf(mx1, __shfl_xor_sync(0xffffffff, mx1, 2));
        float nm0 = fmaxf(m0, mx0), nm1 = fmaxf(m1, mx1);
        float al0 = __expf(m0 - nm0), al1 = __expf(m1 - nm1);
        float rs0 = 0.f, rs1 = 0.f;
        #pragma unroll
        for (int ni = 0; ni < 8; ni++) {
            sacc[ni][0] = __expf(sacc[ni][0] - nm0);
            sacc[ni][1] = __expf(sacc[ni][1] - nm0);
            sacc[ni][2] = __expf(sacc[ni][2] - nm1);
            sacc[ni][3] = __expf(sacc[ni][3] - nm1);
            rs0 += sacc[ni][0] + sacc[ni][1];
            rs1 += sacc[ni][2] + sacc[ni][3];
        }
        rs0 += __shfl_xor_sync(0xffffffff, rs0, 1);
        rs0 += __shfl_xor_sync(0xffffffff, rs0, 2);
        rs1 += __shfl_xor_sync(0xffffffff, rs1, 1);
        rs1 += __shfl_xor_sync(0xffffffff, rs1, 2);
        l0 = l0 * al0 + rs0;  l1 = l1 * al1 + rs1;
        m0 = nm0;  m1 = nm1;
        #pragma unroll
        for (int nd = 0; nd < 8; nd++) {
            oacc[nd][0] *= al0; oacc[nd][1] *= al0;
            oacc[nd][2] *= al1; oacc[nd][3] *= al1;
        }

        #pragma unroll
        for (int kk = 0; kk < 4; kk++) {
            uint32_t ph[4], pl[4];
            cvt_hl(sacc[2*kk][0],   sacc[2*kk][1],   ph[0], pl[0]);
            cvt_hl(sacc[2*kk][2],   sacc[2*kk][3],   ph[1], pl[1]);
            cvt_hl(sacc[2*kk+1][0], sacc[2*kk+1][1], ph[2], pl[2]);
            cvt_hl(sacc[2*kk+1][2], sacc[2*kk+1][3], ph[3], pl[3]);
            #pragma unroll
            for (int nd = 0; nd < 8; nd++) {
                uint32_t vh[2], vl[2];
                int off = (nd * 8 + g) * FA_SK + kk * 8 + tg;
                vh[0] = vhw[off]; vh[1] = vhw[off + 4];
                vl[0] = vlw[off]; vl[1] = vlw[off + 4];
                mma_bf16(oacc[nd], ph, vh);
                mma_bf16(oacc[nd], ph, vl);
                mma_bf16(oacc[nd], pl, vh);
            }
        }
        __syncthreads();
    }

    // ---- fused epilogue: O normalize -> per-token Mqi apply -> om hi/lo ----
    float il0 = 1.0f / l0, il1 = 1.0f / l1;
    const int n = nh / NH, h = nh % NH;
    const bool evenLane = (tg & 1) == 0;
    const int myrow = evenLane ? row0 : row0 + 8;
    const int t = q0 + myrow;
    const float* Mp = Mqi + ((size_t)(n * LTOK + t)) * 16;
    float Mr[16];
    #pragma unroll
    for (int i = 0; i < 16; i++) Mr[i] = Mp[i];
    const size_t rowbase = ((size_t)(n * LTOK + t)) * CC + h * HD;

    #pragma unroll
    for (int nd = 0; nd < 8; nd++) {
        float a0 = oacc[nd][0] * il0, a1 = oacc[nd][1] * il0;
        float b0 = oacc[nd][2] * il1, b1 = oacc[nd][3] * il1;
        float pa0 = __shfl_xor_sync(0xffffffff, a0, 1);
        float pa1 = __shfl_xor_sync(0xffffffff, a1, 1);
        float pb0 = __shfl_xor_sync(0xffffffff, b0, 1);
        float pb1 = __shfl_xor_sync(0xffffffff, b1, 1);
        float s0, s1, s2, s3;
        if (evenLane) { s0 = a0;  s1 = a1;  s2 = pa0; s3 = pa1; }
        else          { s0 = pb0; s1 = pb1; s2 = b0;  s3 = b1;  }
        int base = nd * 8 + (tg >> 1) * 4;
        float d0 = Mr[0]*s0  + Mr[1]*s1  + Mr[2]*s2  + Mr[3]*s3;
        float d1 = Mr[4]*s0  + Mr[5]*s1  + Mr[6]*s2  + Mr[7]*s3;
        float d2 = Mr[8]*s0  + Mr[9]*s1  + Mr[10]*s2 + Mr[11]*s3;
        float d3 = Mr[12]*s0 + Mr[13]*s1 + Mr[14]*s2 + Mr[15]*s3;
        uint32_t h0, lo0, h1, lo1;
        cvt_hl(d0, d1, h0, lo0);
        cvt_hl(d2, d3, h1, lo1);
        size_t w = (rowbase + base) >> 1;
        omh[w] = h0;     oml[w] = lo0;
        omh[w + 1] = h1; oml[w + 1] = lo1;
    }
}

// ---------------- layout kernels ----------------
__global__ void k_build_x(const float* __restrict__ f, float* __restrict__ x,
                          uint32_t* __restrict__ xh, uint32_t* __restrict__ xl,
                          uint32_t* __restrict__ xph, uint32_t* __restrict__ xpl) {
    int idx = blockIdx.x * blockDim.x + threadIdx.x;
    if (idx >= XW) return;
    int c2 = idx & 127;
    int l  = (idx >> 7) & (LTOK-1);
    int n  = idx >> 17;
    int c  = c2 * 2;
    float a = f[((size_t)n*CC + c)*LTOK + l];
    float b = f[((size_t)n*CC + c + 1)*LTOK + l];
    reinterpret_cast<float2*>(x)[idx] = make_float2(a, b);
    uint32_t h, lw;
    cvt_hl(a, b, h, lw);
    xh[idx] = h; xl[idx] = lw;
    xph[idx] = h; xpl[idx] = lw;
}

__global__ void k_final(const float* __restrict__ x, float* __restrict__ o) {
    int idx = blockIdx.x * blockDim.x + threadIdx.x;
    if (idx >= ROWS_*CC) return;
    int l = idx & (LTOK-1);
    int c = (idx >> 10) & (CC-1);
    int n = idx >> 18;
    o[idx] = x[((size_t)n*LTOK + l)*CC + c];
}

// ---------------- PRoPE matrix build ----------------
__device__ __forceinline__ void prope_forward(const float* vm, const float* Kc,
                                              float u, float vyy, float* M) {
    float fx = Kc[0] * (1.0f/128.0f), fy = Kc[4] * (1.0f/128.0f);
    float cx = Kc[2] * (1.0f/128.0f), cy = Kc[5] * (1.0f/128.0f);
    float a = cx - u, b = cy - vyy;
    #pragma unroll
    for (int c = 0; c < 4; c++) {
        M[0*4+c] = fx*vm[0*4+c] + a*vm[2*4+c];
        M[1*4+c] = fy*vm[1*4+c] + b*vm[2*4+c];
        M[2*4+c] = vm[2*4+c];
        M[3*4+c] = vm[3*4+c];
    }
}

__global__ void k_prope_q(const float* __restrict__ vms, const float* __restrict__ Ks,
                          float* __restrict__ Mq, float* __restrict__ Mqi) {
    int idx = blockIdx.x * blockDim.x + threadIdx.x;
    if (idx >= NVB*LTOK) return;
    int n = idx >> 10, t = idx & (LTOK-1);
    int px = t & 31, py = t >> 5;
    float u  = (px + 0.5f) * (1.0f/32.0f);
    float vy = (py + 0.5f) * (1.0f/32.0f);
    const float* vm = vms + n*16;
    const float* Kc = Ks + n*9;
    float M[16];
    prope_forward(vm, Kc, u, vy, M);
    #pragma unroll
    for (int i = 0; i < 16; i++) Mq[idx*16+i] = M[i];

    float r00=vm[0],r01=vm[1],r02=vm[2],  t0=vm[3];
    float r10=vm[4],r11=vm[5],r12=vm[6],  t1=vm[7];
    float r20=vm[8],r21=vm[9],r22=vm[10], t2=vm[11];
    float det = r00*(r11*r22-r12*r21) - r01*(r10*r22-r12*r20) + r02*(r10*r21-r11*r20);
    float id = 1.0f/det;
    float Ri[9];
    Ri[0]=(r11*r22-r12*r21)*id; Ri[1]=(r02*r21-r01*r22)*id; Ri[2]=(r01*r12-r02*r11)*id;
    Ri[3]=(r12*r20-r10*r22)*id; Ri[4]=(r00*r22-r02*r20)*id; Ri[5]=(r02*r10-r00*r12)*id;
    Ri[6]=(r10*r21-r11*r20)*id; Ri[7]=(r01*r20-r00*r21)*id; Ri[8]=(r00*r11-r01*r10)*id;
    float ti0 = -(Ri[0]*t0 + Ri[1]*t1 + Ri[2]*t2);
    float ti1 = -(Ri[3]*t0 + Ri[4]*t1 + Ri[5]*t2);
    float ti2 = -(Ri[6]*t0 + Ri[7]*t1 + Ri[8]*t2);
    float fx = Kc[0]*(1.0f/128.0f), fy = Kc[4]*(1.0f/128.0f);
    float cx = Kc[2]*(1.0f/128.0f), cy = Kc[5]*(1.0f/128.0f);
    float a = cx - u, b = cy - vy;
    float ifx = 1.0f/fx, ify = 1.0f/fy;
    float Mi[16];
    float tv[3] = {ti0, ti1, ti2};
    #pragma unroll
    for (int i = 0; i < 3; i++) {
        Mi[i*4+0] = Ri[i*3+0]*ifx;
        Mi[i*4+1] = Ri[i*3+1]*ify;
        Mi[i*4+2] = -Ri[i*3+0]*a*ifx - Ri[i*3+1]*b*ify + Ri[i*3+2];
        Mi[i*4+3] = tv[i];
    }
    Mi[12]=0.f; Mi[13]=0.f; Mi[14]=0.f; Mi[15]=1.f;
    #pragma unroll
    for (int i = 0; i < 16; i++) Mqi[idx*16+i] = Mi[i];
}

__global__ void k_prope_kv(const float* __restrict__ vms, const float* __restrict__ Ks,
                           float* __restrict__ Mkv) {
    int idx = blockIdx.x * blockDim.x + threadIdx.x;
    if (idx >= NVB*TKX) return;
    int n = idx >> 11, tt = idx & (TKX-1);
    int m = tt >> 10, l = tt & (LTOK-1);
    int vvi = n >> 1, b = n & 1;
    int j = m + (m >= vvi ? 1 : 0);
    int cam = j*BB + b;
    int px = l & 31, py = l >> 5;
    float u  = (px + 0.5f)*(1.0f/32.0f);
    float vy = (py + 0.5f)*(1.0f/32.0f);
    float M[16];
    prope_forward(vms + cam*16, Ks + cam*9, u, vy, M);
    #pragma unroll
    for (int i = 0; i < 16; i++) Mkv[idx*16+i] = M[i];
}

// ---------------- fused per-token applies (packed Q/K/V outputs) -------------
__global__ void k_apply_all(const float* __restrict__ qkv, int stride,
                            const float* __restrict__ Mqi, const float* __restrict__ Mats,
                            uint32_t* __restrict__ qph, uint32_t* __restrict__ qpl,
                            uint32_t* __restrict__ kph, uint32_t* __restrict__ kpl,
                            uint32_t* __restrict__ vph, uint32_t* __restrict__ vpl,
                            int Tk, int gather, int nkv)
{
    int idx = blockIdx.x * blockDim.x + threadIdx.x;
    if (idx < NAPP) {
        int g = idx & 15, h = (idx >> 4) & 3, t = (idx >> 6) & (LTOK-1), n = idx >> 16;
        const float* M = Mqi + ((size_t)(n*LTOK + t))*16;
        const float* s = qkv + ((size_t)(n*LTOK + t))*stride + h*HD + g*4;
        float x0=s[0], x1=s[1], x2=s[2], x3=s[3];
        float d[4];
        #pragma unroll
        for (int i = 0; i < 4; i++)
            d[i] = M[0*4+i]*x0 + M[1*4+i]*x1 + M[2*4+i]*x2 + M[3*4+i]*x3;
        // scale by 1/8 and pack (identical to previous in-flash conversion)
        uint32_t h0, l0, h1, l1;
        cvt_hl(d[0]*0.125f, d[1]*0.125f, h0, l0);
        cvt_hl(d[2]*0.125f, d[3]*0.125f, h1, l1);
        size_t wb = (((size_t)(n*NH + h))*LTOK + t)*32 + g*2;
        qph[wb] = h0;   qpl[wb] = l0;
        qph[wb+1] = h1; qpl[wb+1] = l1;
    } else if (idx < NAPP + nkv) {
        int i2 = idx - NAPP;
        int g = i2 & 15, h = (i2 >> 4) & 3;
        int tt = (i2 >> 6) % Tk, n = (i2 >> 6) / Tk;
        size_t srcRow;
        if (gather) {
            int m = tt >> 10, l = tt & (LTOK-1);
            int vvi = n >> 1, b = n & 1;
            int j = m + (m >= vvi ? 1 : 0);
            srcRow = (size_t)(j*BB + b)*LTOK + l;
        } else {
            srcRow = (size_t)n*LTOK + tt;
        }
        const float* M = Mats + ((size_t)n*Tk + tt)*16;
        const float* s = qkv + srcRow*stride + 256 + h*HD + g*4;
        float x0=s[0], x1=s[1], x2=s[2], x3=s[3];
        float d[4];
        #pragma unroll
        for (int i = 0; i < 4; i++)
            d[i] = M[i*4+0]*x0 + M[i*4+1]*x1 + M[i*4+2]*x2 + M[i*4+3]*x3;
        size_t wb = (((size_t)(n*NH + h))*Tk + tt)*32 + g*2;
        uint32_t h0, l0, h1, l1;
        cvt_hl(d[0], d[1], h0, l0);
        cvt_hl(d[2], d[3], h1, l1);
        kph[wb] = h0;   kpl[wb] = l0;
        kph[wb+1] = h1; kpl[wb+1] = l1;
    } else if (idx < NAPP + 2*nkv) {
        int i2 = idx - NAPP - nkv;
        int tt = i2 % Tk;
        int rest = i2 / Tk;
        int g = rest & 15, h = (rest >> 4) & 3, n = rest >> 6;
        size_t srcRow;
        if (gather) {
            int m = tt >> 10, l = tt & (LTOK-1);
            int vvi = n >> 1, b = n & 1;
            int j = m + (m >= vvi ? 1 : 0);
            srcRow = (size_t)(j*BB + b)*LTOK + l;
        } else {
            srcRow = (size_t)n*LTOK + tt;
        }
        const float* M = Mats + ((size_t)n*Tk + tt)*16;
        const float* s = qkv + srcRow*stride + 512 + h*HD + g*4;
        float x0=s[0], x1=s[1], x2=s[2], x3=s[3];
        #pragma unroll
        for (int i = 0; i < 4; i++) {
            float v = M[i*4+0]*x0 + M[i*4+1]*x1 + M[i*4+2]*x2 + M[i*4+3]*x3;
            float vn = __shfl_down_sync(0xffffffff, v, 1);
            if ((tt & 1) == 0) {
                uint32_t hh2, ll2;
                cvt_hl(v, vn, hh2, ll2);
                size_t wb = ((size_t)(n*NH + h)*HD + g*4 + i)*(Tk >> 1) + (tt >> 1);
                vph[wb] = hh2; vpl[wb] = ll2;
            }
        }
    }
}

// ---------------- layernorm: sums nparts partials, optional bf16 + cat writes --
__global__ void k_ln(float* __restrict__ dst, const float* __restrict__ parts, int nparts,
                     const float* __restrict__ w, const float* __restrict__ b, int add,
                     uint32_t* __restrict__ oh, uint32_t* __restrict__ ol,
                     uint32_t* __restrict__ oh2, uint32_t* __restrict__ ol2,
                     uint32_t* __restrict__ ch, uint32_t* __restrict__ cl, int catHalf) {
    __shared__ float red[256];
    int row = blockIdx.x, tid = threadIdx.x;
    float v = parts[(size_t)row*CC + tid];
    for (int p = 1; p < nparts; p++)
        v += parts[(size_t)p*ROWS_*CC + (size_t)row*CC + tid];
    red[tid] = v; __syncthreads();
    for (int s = 128; s > 0; s >>= 1) { if (tid < s) red[tid] += red[tid+s]; __syncthreads(); }
    float mu = red[0] * (1.0f/CC); __syncthreads();
    float d = v - mu;
    red[tid] = d * d; __syncthreads();
    for (int s = 128; s > 0; s >>= 1) { if (tid < s) red[tid] += red[tid+s]; __syncthreads(); }
    float var = red[0] * (1.0f/CC);
    float o = d * rsqrtf(var + 1e-5f) * w[tid] + b[tid];
    float fin;
    if (add) { fin = dst[(size_t)row*CC + tid] + o; dst[(size_t)row*CC + tid] = fin; }
    else     { fin = o; dst[(size_t)row*CC + tid] = fin; }
    if (oh || ch) {
        __syncthreads();
        red[tid] = fin;
        __syncthreads();
        if (tid < 128) {
            uint32_t h, l;
            cvt_hl(red[2*tid], red[2*tid+1], h, l);
            if (oh) {
                oh[(size_t)row*(CC/2) + tid] = h;
                ol[(size_t)row*(CC/2) + tid] = l;
                if (oh2) {
                    oh2[(size_t)row*(CC/2) + tid] = h;
                    ol2[(size_t)row*(CC/2) + tid] = l;
                }
            }
            if (ch) {
                size_t cw = (size_t)row*(FFNI/2) + catHalf*128 + tid;
                ch[cw] = h; cl[cw] = l;
            }
        }
    }
}

// ---------------- host driver ----------------
static const int GSMEM128 = 98304;
static const int GSMEM64  = 73728;

static void gemm128(const uint32_t* Ah, const uint32_t* Al,
                    const uint32_t* A2h, const uint32_t* A2l, int nsplit,
                    const uint32_t* Bh, const uint32_t* Bl,
                    float* C, int M, int N, int K) {
    dim3 g(N/128, M/128, 1);
    tc_gemm<128,0><<<g, 256, GSMEM128>>>(Ah, Al, A2h, A2l, nsplit, Bh, Bl,
                                         C, nullptr, nullptr, M, N, K, K);
}
static void gemm64s(const uint32_t* Ah, const uint32_t* Al,
                    const uint32_t* Bh, const uint32_t* Bl,
                    float* C, int M, int N, int Ktot, int nz) {
    dim3 g(N/64, M/128, nz);
    tc_gemm<64,0><<<g, 256, GSMEM64>>>(Ah, Al, Ah, Al, 1<<30, Bh, Bl,
                                       C, nullptr, nullptr, M, N, Ktot/nz, Ktot);
}
static void gemm_gelu_hl(const uint32_t* Ah, const uint32_t* Al,
                         const uint32_t* Bh, const uint32_t* Bl,
                         uint32_t* Oh, uint32_t* Ol, int M, int N, int K) {
    dim3 g(N/128, M/128, 1);
    tc_gemm<128,1><<<g, 256, GSMEM128>>>(Ah, Al, Ah, Al, 1<<30, Bh, Bl,
                                         nullptr, Oh, Ol, M, N, K, K);
}

extern "C" void kernel_launch(void* const* d_in, const int* in_sizes, int n_in,
                              void* d_out, int out_size) {
    const float* feats = (const float*)d_in[0];
    const float* vms   = (const float*)d_in[1];
    const float* Ks    = (const float*)d_in[2];
    const float* Wq    = (const float*)d_in[3];
    const float* Wk    = (const float*)d_in[4];
    const float* Wv    = (const float*)d_in[5];
    const float* Wm    = (const float*)d_in[6];
    const float* n1w   = (const float*)d_in[7];
    const float* n1b   = (const float*)d_in[8];
    const float* W1    = (const float*)d_in[9];
    const float* W2    = (const float*)d_in[10];
    const float* n2w   = (const float*)d_in[11];
    const float* n2b   = (const float*)d_in[12];

    cudaFuncSetAttribute(tc_gemm<128,0>, cudaFuncAttributeMaxDynamicSharedMemorySize, GSMEM128);
    cudaFuncSetAttribute(tc_gemm<128,1>, cudaFuncAttributeMaxDynamicSharedMemorySize, GSMEM128);
    cudaFuncSetAttribute(tc_gemm<64,0>,  cudaFuncAttributeMaxDynamicSharedMemorySize, GSMEM64);

    void* p;
    float *x,*qkv,*msg,*msg2,*h22,*Mq,*Mqi,*Mkv;
    uint32_t *qph,*qpl,*kph,*kpl,*vph,*vpl;
    uint32_t *xh,*xl,*xpreh,*xprel,*omh,*oml,*cath,*catl,*hh,*hl,*wh,*wl;
    cudaGetSymbolAddress(&p, g_x);    x   = (float*)p;
    cudaGetSymbolAddress(&p, g_qkv);  qkv = (float*)p;
    cudaGetSymbolAddress(&p, g_qph);  qph = (uint32_t*)p;
    cudaGetSymbolAddress(&p, g_qpl);  qpl = (uint32_t*)p;
    cudaGetSymbolAddress(&p, g_kph);  kph = (uint32_t*)p;
    cudaGetSymbolAddress(&p, g_kpl);  kpl = (uint32_t*)p;
    cudaGetSymbolAddress(&p, g_vph);  vph = (uint32_t*)p;
    cudaGetSymbolAddress(&p, g_vpl);  vpl = (uint32_t*)p;
    cudaGetSymbolAddress(&p, g_msg);  msg = (float*)p;
    cudaGetSymbolAddress(&p, g_msg2); msg2= (float*)p;
    cudaGetSymbolAddress(&p, g_h22);  h22 = (float*)p;
    cudaGetSymbolAddress(&p, g_Mq);   Mq  = (float*)p;
    cudaGetSymbolAddress(&p, g_Mqi);  Mqi = (float*)p;
    cudaGetSymbolAddress(&p, g_Mkv);  Mkv = (float*)p;
    cudaGetSymbolAddress(&p, g_xh);    xh    = (uint32_t*)p;
    cudaGetSymbolAddress(&p, g_xl);    xl    = (uint32_t*)p;
    cudaGetSymbolAddress(&p, g_xpreh); xpreh = (uint32_t*)p;
    cudaGetSymbolAddress(&p, g_xprel); xprel = (uint32_t*)p;
    cudaGetSymbolAddress(&p, g_omh);   omh   = (uint32_t*)p;
    cudaGetSymbolAddress(&p, g_oml);   oml   = (uint32_t*)p;
    cudaGetSymbolAddress(&p, g_cath);  cath  = (uint32_t*)p;
    cudaGetSymbolAddress(&p, g_catl);  catl  = (uint32_t*)p;
    cudaGetSymbolAddress(&p, g_hh);    hh    = (uint32_t*)p;
    cudaGetSymbolAddress(&p, g_hl);    hl    = (uint32_t*)p;
    cudaGetSymbolAddress(&p, g_wh);    wh    = (uint32_t*)p;
    cudaGetSymbolAddress(&p, g_wl);    wl    = (uint32_t*)p;

    const int ROWS = ROWS_;
    const int NEL  = ROWS * CC;
    const int NKV_SELF  = NAPP;
    const int NKV_CROSS = NVB*TKX*NH*16;

    k_cvt_all<<<WTOT/256, 256>>>(Wq, Wk, Wv, Wm, W1, W2, wh, wl);
    k_build_x<<<(XW+255)/256, 256>>>(feats, x, xh, xl, xpreh, xprel);
    k_prope_q<<<(ROWS+255)/256, 256>>>(vms, Ks, Mq, Mqi);
    k_prope_kv<<<(NVB*TKX+255)/256, 256>>>(vms, Ks, Mkv);

    for (int ly = 0; ly < 2; ly++) {
        // ---------- self attention ----------
        gemm128(xh, xl, xh, xl, 1<<30,
                wh + WQKV0 + (ly*2+0)*98304, wl + WQKV0 + (ly*2+0)*98304,
                qkv, ROWS, 768, CC);
        k_apply_all<<<(NAPP + 2*NKV_SELF)/256, 256>>>(
            qkv, 768, Mqi, Mq, qph, qpl, kph, kpl, vph, vpl, LTOK, 0, NKV_SELF);
        k_flash<<<dim3(LTOK/128, NVB*NH), 256>>>(qph, qpl, kph, kpl, vph, vpl,
                                                 Mqi, omh, oml, LTOK);
        gemm64s(omh, oml, wh + WMO + (ly*2+0)*32768, wl + WMO + (ly*2+0)*32768,
                msg2, ROWS, CC, CC, 2);
        k_ln<<<ROWS, 256>>>(x, msg2, 2, n1w + (ly*2+0)*CC, n1b + (ly*2+0)*CC, 1,
                            xh, xl, nullptr, nullptr, cath, catl, 0);

        // ---------- cross attention ----------
        gemm128(xh, xl, xpreh, xprel, 256,
                wh + WQKV0 + (ly*2+1)*98304, wl + WQKV0 + (ly*2+1)*98304,
                qkv, ROWS, 768, CC);
        k_apply_all<<<(NAPP + 2*NKV_CROSS)/256, 256>>>(
            qkv, 768, Mqi, Mkv, qph, qpl, kph, kpl, vph, vpl, TKX, 1, NKV_CROSS);
        k_flash<<<dim3(LTOK/128, NVB*NH), 256>>>(qph, qpl, kph, kpl, vph, vpl,
                                                 Mqi, omh, oml, TKX);
        gemm64s(omh, oml, wh + WMO + (ly*2+1)*32768, wl + WMO + (ly*2+1)*32768,
                msg2, ROWS, CC, CC, 2);
        k_ln<<<ROWS, 256>>>(msg, msg2, 2, n1w + (ly*2+1)*CC, n1b + (ly*2+1)*CC, 0,
                            nullptr, nullptr, nullptr, nullptr, cath, catl, 1);

        // ---------- FFN ----------
        gemm_gelu_hl(cath, catl,
                     wh + W1O + (size_t)ly*524288, wl + W1O + (size_t)ly*524288,
                     hh, hl, ROWS, FFNH, FFNI);
        gemm64s(hh, hl, wh + W2O + (size_t)ly*262144, wl + W2O + (size_t)ly*262144,
                h22, ROWS, CC, FFNH, 4);
        k_ln<<<ROWS, 256>>>(x, h22, 4, n2w + ly*CC, n2b + ly*CC, 1,
                            xh, xl, xpreh, xprel, nullptr, nullptr, 0);
    }

    k_final<<<(NEL+255)/256, 256>>>(x, (float*)d_out);
}

// round 15
// speedup vs baseline: 1.0074x; 1.0074x over previous
#include <cuda_runtime.h>
#include <cuda_bf16.h>
#include <math.h>
#include <stdint.h>

// ---------------- problem constants ----------------
#define NVB   6
#define VV    3
#define BB    2
#define CC    256
#define LTOK  1024
#define TKX   2048
#define NH    4
#define HD    64
#define FFNI  512
#define FFNH  2048

#define ROWS_ (NVB*LTOK)          // 6144
#define XW    (NVB*LTOK*CC/2)
#define NAPP  (NVB*LTOK*NH*16)    // 393216

// ---------------- device scratch ----------------
__device__ float g_x   [ROWS_*CC];
__device__ float g_qkv [ROWS_*768];
__device__ uint32_t g_qph[NVB*NH*LTOK*32], g_qpl[NVB*NH*LTOK*32];
__device__ uint32_t g_kph[NVB*NH*TKX*HD/2], g_kpl[NVB*NH*TKX*HD/2];
__device__ uint32_t g_vph[NVB*NH*TKX*HD/2], g_vpl[NVB*NH*TKX*HD/2];  // V^T packed
__device__ float g_O   [NVB*NH*LTOK*HD];
__device__ float g_msg [ROWS_*CC];
__device__ float g_msg2[2*ROWS_*CC];          // split-K partials (msg)
__device__ float g_h22 [4*ROWS_*CC];          // split-K partials (W2, x4)
__device__ float g_Mq  [NVB*LTOK*16];
__device__ float g_Mqi [NVB*LTOK*16];
__device__ float g_Mkv [NVB*TKX*16];

__device__ uint32_t g_xh   [XW],  g_xl   [XW];
__device__ uint32_t g_xpreh[XW],  g_xprel[XW];
__device__ uint32_t g_omh  [XW],  g_oml  [XW];
__device__ uint32_t g_cath [ROWS_*FFNI/2], g_catl[ROWS_*FFNI/2];
__device__ uint32_t g_hh   [ROWS_*FFNH/2], g_hl  [ROWS_*FFNH/2];
#define WQKV0 0
#define WMO   393216
#define W1O   524288
#define W2O   1572864
#define WTOT  2097152
__device__ uint32_t g_wh[WTOT], g_wl[WTOT];

// ---------------- helpers ----------------
__device__ __forceinline__ void cvt_hl(float x, float y, uint32_t& hi, uint32_t& lo) {
    __nv_bfloat162 h = __floats2bfloat162_rn(x, y);
    float rx = x - __bfloat162float(h.x);
    float ry = y - __bfloat162float(h.y);
    __nv_bfloat162 l = __floats2bfloat162_rn(rx, ry);
    hi = *reinterpret_cast<uint32_t*>(&h);
    lo = *reinterpret_cast<uint32_t*>(&l);
}

__device__ __forceinline__ void mma_bf16(float* c, const uint32_t* a, const uint32_t* b) {
    asm volatile(
        "mma.sync.aligned.m16n8k16.row.col.f32.bf16.bf16.f32 "
        "{%0,%1,%2,%3}, {%4,%5,%6,%7}, {%8,%9}, {%0,%1,%2,%3};"
        : "+f"(c[0]), "+f"(c[1]), "+f"(c[2]), "+f"(c[3])
        : "r"(a[0]), "r"(a[1]), "r"(a[2]), "r"(a[3]), "r"(b[0]), "r"(b[1]));
}

__device__ __forceinline__ void ldsm4(uint32_t* r, uint32_t addr) {
    asm volatile("ldmatrix.sync.aligned.m8n8.x4.shared.b16 {%0,%1,%2,%3}, [%4];"
        : "=r"(r[0]), "=r"(r[1]), "=r"(r[2]), "=r"(r[3]) : "r"(addr));
}

__device__ __forceinline__ uint32_t smem_u32(const void* p) {
    uint32_t a;
    asm("{ .reg .u64 t; cvta.to.shared.u64 t, %1; cvt.u32.u64 %0, t; }" : "=r"(a) : "l"(p));
    return a;
}

__device__ __forceinline__ void cp16(uint32_t smem, const void* g) {
    asm volatile("cp.async.cg.shared.global [%0], [%1], 16;" :: "r"(smem), "l"(g));
}
#define CP_COMMIT() asm volatile("cp.async.commit_group;")
#define CP_WAIT(N)  asm volatile("cp.async.wait_group %0;" :: "n"(N))

// ---------------- all-weight conversion + QKV repack ----------------
__global__ void k_cvt_all(const float* __restrict__ Wq, const float* __restrict__ Wk,
                          const float* __restrict__ Wv, const float* __restrict__ Wm,
                          const float* __restrict__ W1, const float* __restrict__ W2,
                          uint32_t* __restrict__ wh, uint32_t* __restrict__ wl) {
    int i = blockIdx.x * blockDim.x + threadIdx.x;
    if (i >= WTOT) return;
    const float* src;
    if (i < WMO) {
        int lyp  = i / 98304;
        int sub  = i % 98304;
        int which = sub / 32768;
        int woff  = sub % 32768;
        const float* base = (which == 0) ? Wq : (which == 1) ? Wk : Wv;
        src = base + (size_t)lyp * 65536 + (size_t)woff * 2;
    } else if (i < W1O) {
        src = Wm + (size_t)(i - WMO) * 2;
    } else if (i < W2O) {
        src = W1 + (size_t)(i - W1O) * 2;
    } else {
        src = W2 + (size_t)(i - W2O) * 2;
    }
    float2 v = *reinterpret_cast<const float2*>(src);
    uint32_t h, l;
    cvt_hl(v.x, v.y, h, l);
    wh[i] = h; wl[i] = l;
}

// ---------------- tensor-core bf16x3 GEMM (BN template, split-K via z) -------
template<int BN, int OUT>
__global__ __launch_bounds__(256)
void tc_gemm(const uint32_t* __restrict__ Ah, const uint32_t* __restrict__ Al,
             const uint32_t* __restrict__ A2h, const uint32_t* __restrict__ A2l,
             int nsplit,
             const uint32_t* __restrict__ Bh, const uint32_t* __restrict__ Bl,
             float* __restrict__ C, uint32_t* __restrict__ Oh, uint32_t* __restrict__ Ol,
             int M, int N, int K, int Krow)
{
    constexpr int WARPS_N = BN / 32;
    constexpr int WMX = 128 / (8 / WARPS_N);
    constexpr int MT = WMX / 16;
    constexpr int B_HI = BN * 48;
    constexpr int STAGE = 12288 + 2 * B_HI;

    extern __shared__ uint32_t smem[];
    const uint32_t sb0 = smem_u32(smem);

    const int m0 = blockIdx.y * 128;
    const int n0 = blockIdx.x * BN;
    const int kz = blockIdx.z;
    const int tid = threadIdx.x;
    const int wid = tid >> 5, lane = tid & 31;
    const int g = lane >> 2, tg = lane & 3;
    const int warp_m = wid / WARPS_N, warp_n = wid % WARPS_N;
    const int wm0 = warp_m * WMX, wn0 = warp_n * 32;
    const int Krow2 = Krow >> 1;
    const size_t kzoff = (size_t)kz * (K >> 1);

    const int rowa = tid >> 1, hw = (tid & 1) * 4;

    const int a_lrow = lane & 15;
    const int a_lcol = (lane >> 4) * 4;
    const int b_lrow = (lane & 7) + ((lane >> 4) << 3);
    const int b_lcol = ((lane >> 3) & 1) * 4;

    float acc[MT][4][4];
    #pragma unroll
    for (int i = 0; i < MT; i++)
        #pragma unroll
        for (int j = 0; j < 4; j++)
            #pragma unroll
            for (int r = 0; r < 4; r++) acc[i][j][r] = 0.f;

    const bool useA2 = (n0 >= nsplit);
    const uint32_t* Ab  = (useA2 ? A2h : Ah) + (size_t)(m0 + rowa) * Krow2 + hw + kzoff;
    const uint32_t* Alb = (useA2 ? A2l : Al) + (size_t)(m0 + rowa) * Krow2 + hw + kzoff;
    const uint32_t* Bb  = Bh + (size_t)(n0 + rowa) * Krow2 + hw + kzoff;
    const uint32_t* Blb = Bl + (size_t)(n0 + rowa) * Krow2 + hw + kzoff;
    C += (size_t)kz * M * N;

    const uint32_t dst_off = (uint32_t)(rowa * 12 + hw) * 4;
    const int nk = K >> 4;

    #define ISSUE(tile, stage) do {                                   \
        uint32_t sb = sb0 + (stage) * (uint32_t)STAGE;                \
        int ko = (tile) * 8;                                          \
        cp16(sb + dst_off,        Ab + ko);                           \
        cp16(sb + 6144 + dst_off, Alb + ko);                          \
        if (BN == 128 || tid < 128) {                                 \
            cp16(sb + 12288 + dst_off,        Bb + ko);               \
            cp16(sb + 12288 + B_HI + dst_off, Blb + ko);              \
        }                                                             \
    } while (0)

    #pragma unroll
    for (int s = 0; s < 3; s++) {
        if (s < nk) ISSUE(s, s);
        CP_COMMIT();
    }

    for (int kt = 0; kt < nk; kt++) {
        if (kt + 3 < nk) ISSUE(kt + 3, (kt + 3) & 3);
        CP_COMMIT();
        CP_WAIT(3);
        __syncthreads();

        const uint32_t sb = sb0 + (kt & 3) * (uint32_t)STAGE;
        uint32_t ah[MT][4], al[MT][4], bh2[4][2], bl2[4][2];
        #pragma unroll
        for (int mi = 0; mi < MT; mi++) {
            uint32_t woff = (uint32_t)((wm0 + mi*16 + a_lrow) * 12 + a_lcol) * 4;
            ldsm4(ah[mi], sb + woff);
            ldsm4(al[mi], sb + 6144 + woff);
        }
        #pragma unroll
        for (int p = 0; p < 2; p++) {
            uint32_t woff = (uint32_t)((wn0 + p*16 + b_lrow) * 12 + b_lcol) * 4;
            uint32_t r[4];
            ldsm4(r, sb + 12288 + woff);
            bh2[2*p][0] = r[0]; bh2[2*p][1] = r[1];
            bh2[2*p+1][0] = r[2]; bh2[2*p+1][1] = r[3];
            ldsm4(r, sb + 12288 + B_HI + woff);
            bl2[2*p][0] = r[0]; bl2[2*p][1] = r[1];
            bl2[2*p+1][0] = r[2]; bl2[2*p+1][1] = r[3];
        }
        #pragma unroll
        for (int mi = 0; mi < MT; mi++)
            #pragma unroll
            for (int ni = 0; ni < 4; ni++) {
                mma_bf16(acc[mi][ni], ah[mi], bh2[ni]);
                mma_bf16(acc[mi][ni], ah[mi], bl2[ni]);
                mma_bf16(acc[mi][ni], al[mi], bh2[ni]);
            }
        __syncthreads();
    }
    #undef ISSUE

    #pragma unroll
    for (int mi = 0; mi < MT; mi++) {
        #pragma unroll
        for (int ni = 0; ni < 4; ni++) {
            long long row0 = m0 + wm0 + mi * 16 + g;
            int col = n0 + wn0 + ni * 8 + tg * 2;
            if (OUT == 0) {
                *reinterpret_cast<float2*>(&C[row0 * N + col]) =
                    make_float2(acc[mi][ni][0], acc[mi][ni][1]);
                *reinterpret_cast<float2*>(&C[(row0 + 8) * N + col]) =
                    make_float2(acc[mi][ni][2], acc[mi][ni][3]);
            } else {
                float r[4];
                #pragma unroll
                for (int t = 0; t < 4; t++) {
                    float v = acc[mi][ni][t];
                    r[t] = 0.5f * v * (1.0f + erff(v * 0.70710678118654752f));
                }
                uint32_t h0, l0, h1, l1;
                cvt_hl(r[0], r[1], h0, l0);
                cvt_hl(r[2], r[3], h1, l1);
                size_t w0 = (size_t)(row0 * N + col) >> 1;
                size_t w1 = (size_t)((row0 + 8) * N + col) >> 1;
                Oh[w0] = h0; Ol[w0] = l0;
                Oh[w1] = h1; Ol[w1] = l1;
            }
        }
    }
}

// ---------------- fused flash attention (packed Q/K/V, fp32 O out) ----------
#define FA_SK 36
__global__ __launch_bounds__(256)
void k_flash(const uint32_t* __restrict__ qph, const uint32_t* __restrict__ qpl,
             const uint32_t* __restrict__ kph, const uint32_t* __restrict__ kpl,
             const uint32_t* __restrict__ vph, const uint32_t* __restrict__ vpl,
             float* __restrict__ Og, int Tk)
{
    __shared__ uint32_t khw[64*FA_SK], klw[64*FA_SK];
    __shared__ uint32_t vhw[64*FA_SK], vlw[64*FA_SK];

    const int nh = blockIdx.y;
    const int q0 = blockIdx.x * 128;
    const int tid = threadIdx.x, wid = tid >> 5, lane = tid & 31;
    const int g = lane >> 2, tg = lane & 3;

    const uint32_t* Qh = qph + ((size_t)nh * LTOK + q0) * 32;
    const uint32_t* Ql = qpl + ((size_t)nh * LTOK + q0) * 32;
    const uint32_t* Kh = kph + (size_t)nh * Tk * 32;
    const uint32_t* Kl = kpl + (size_t)nh * Tk * 32;
    const uint32_t* Vh = vph + (size_t)nh * HD * (Tk >> 1);
    const uint32_t* Vl = vpl + (size_t)nh * HD * (Tk >> 1);

    const int row0 = wid * 16 + g;
    uint32_t qh[4][4], ql[4][4];
    #pragma unroll
    for (int kk = 0; kk < 4; kk++) {
        int w0 = row0 * 32 + kk * 8 + tg;
        int w1 = (row0 + 8) * 32 + kk * 8 + tg;
        qh[kk][0] = Qh[w0];     ql[kk][0] = Ql[w0];
        qh[kk][1] = Qh[w1];     ql[kk][1] = Ql[w1];
        qh[kk][2] = Qh[w0 + 4]; ql[kk][2] = Ql[w0 + 4];
        qh[kk][3] = Qh[w1 + 4]; ql[kk][3] = Ql[w1 + 4];
    }

    float m0 = -1e30f, m1 = -1e30f, l0 = 0.f, l1 = 0.f;
    float oacc[8][4];
    #pragma unroll
    for (int i = 0; i < 8; i++)
        #pragma unroll
        for (int t = 0; t < 4; t++) oacc[i][t] = 0.f;

    const int r = tid >> 2, c2 = (tid & 3) * 8;
    uint4 kh0, kh1, kl0, kl1, vh0, vh1, vl0, vl1;
    {
        const uint32_t* sk = Kh + (size_t)r * 32 + c2;
        const uint32_t* sl = Kl + (size_t)r * 32 + c2;
        const uint32_t* tv = Vh + (size_t)r * (Tk >> 1) + c2;
        const uint32_t* tl = Vl + (size_t)r * (Tk >> 1) + c2;
        kh0 = *reinterpret_cast<const uint4*>(sk);
        kh1 = *reinterpret_cast<const uint4*>(sk + 4);
        kl0 = *reinterpret_cast<const uint4*>(sl);
        kl1 = *reinterpret_cast<const uint4*>(sl + 4);
        vh0 = *reinterpret_cast<const uint4*>(tv);
        vh1 = *reinterpret_cast<const uint4*>(tv + 4);
        vl0 = *reinterpret_cast<const uint4*>(tl);
        vl1 = *reinterpret_cast<const uint4*>(tl + 4);
    }

    for (int kv0 = 0; kv0 < Tk; kv0 += 64) {
        {
            int w = r * FA_SK + c2;
            *reinterpret_cast<uint4*>(&khw[w]) = kh0;
            *reinterpret_cast<uint4*>(&khw[w + 4]) = kh1;
            *reinterpret_cast<uint4*>(&klw[w]) = kl0;
            *reinterpret_cast<uint4*>(&klw[w + 4]) = kl1;
            *reinterpret_cast<uint4*>(&vhw[w]) = vh0;
            *reinterpret_cast<uint4*>(&vhw[w + 4]) = vh1;
            *reinterpret_cast<uint4*>(&vlw[w]) = vl0;
            *reinterpret_cast<uint4*>(&vlw[w + 4]) = vl1;
        }
        __syncthreads();

        if (kv0 + 64 < Tk) {
            const uint32_t* sk = Kh + (size_t)(kv0 + 64 + r) * 32 + c2;
            const uint32_t* sl = Kl + (size_t)(kv0 + 64 + r) * 32 + c2;
            const uint32_t* tv = Vh + (size_t)r * (Tk >> 1) + ((kv0 + 64) >> 1) + c2;
            const uint32_t* tl = Vl + (size_t)r * (Tk >> 1) + ((kv0 + 64) >> 1) + c2;
            kh0 = *reinterpret_cast<const uint4*>(sk);
            kh1 = *reinterpret_cast<const uint4*>(sk + 4);
            kl0 = *reinterpret_cast<const uint4*>(sl);
            kl1 = *reinterpret_cast<const uint4*>(sl + 4);
            vh0 = *reinterpret_cast<const uint4*>(tv);
            vh1 = *reinterpret_cast<const uint4*>(tv + 4);
            vl0 = *reinterpret_cast<const uint4*>(tl);
            vl1 = *reinterpret_cast<const uint4*>(tl + 4);
        }

        float sacc[8][4];
        #pragma unroll
        for (int i = 0; i < 8; i++)
            #pragma unroll
            for (int t = 0; t < 4; t++) sacc[i][t] = 0.f;
        #pragma unroll
        for (int kk = 0; kk < 4; kk++) {
            #pragma unroll
            for (int ni = 0; ni < 8; ni++) {
                uint32_t bh[2], bl[2];
                int off = (ni * 8 + g) * FA_SK + kk * 8 + tg;
                bh[0] = khw[off]; bh[1] = khw[off + 4];
                bl[0] = klw[off]; bl[1] = klw[off + 4];
                mma_bf16(sacc[ni], qh[kk], bh);
                mma_bf16(sacc[ni], qh[kk], bl);
                mma_bf16(sacc[ni], ql[kk], bh);
            }
        }

        float mx0 = -1e30f, mx1 = -1e30f;
        #pragma unroll
        for (int ni = 0; ni < 8; ni++) {
            mx0 = fmaxf(mx0, fmaxf(sacc[ni][0], sacc[ni][1]));
            mx1 = fmaxf(mx1, fmaxf(sacc[ni][2], sacc[ni][3]));
        }
        mx0 = fmaxf(mx0, __shfl_xor_sync(0xffffffff, mx0, 1));
        mx0 = fmaxf(mx0, __shfl_xor_sync(0xffffffff, mx0, 2));
        mx1 = fmaxf(mx1, __shfl_xor_sync(0xffffffff, mx1, 1));
        mx1 = fmaxf(mx1, __shfl_xor_sync(0xffffffff, mx1, 2));
        float nm0 = fmaxf(m0, mx0), nm1 = fmaxf(m1, mx1);
        float al0 = __expf(m0 - nm0), al1 = __expf(m1 - nm1);
        float rs0 = 0.f, rs1 = 0.f;
        #pragma unroll
        for (int ni = 0; ni < 8; ni++) {
            sacc[ni][0] = __expf(sacc[ni][0] - nm0);
            sacc[ni][1] = __expf(sacc[ni][1] - nm0);
            sacc[ni][2] = __expf(sacc[ni][2] - nm1);
            sacc[ni][3] = __expf(sacc[ni][3] - nm1);
            rs0 += sacc[ni][0] + sacc[ni][1];
            rs1 += sacc[ni][2] + sacc[ni][3];
        }
        rs0 += __shfl_xor_sync(0xffffffff, rs0, 1);
        rs0 += __shfl_xor_sync(0xffffffff, rs0, 2);
        rs1 += __shfl_xor_sync(0xffffffff, rs1, 1);
        rs1 += __shfl_xor_sync(0xffffffff, rs1, 2);
        l0 = l0 * al0 + rs0;  l1 = l1 * al1 + rs1;
        m0 = nm0;  m1 = nm1;
        #pragma unroll
        for (int nd = 0; nd < 8; nd++) {
            oacc[nd][0] *= al0; oacc[nd][1] *= al0;
            oacc[nd][2] *= al1; oacc[nd][3] *= al1;
        }

        #pragma unroll
        for (int kk = 0; kk < 4; kk++) {
            uint32_t ph[4], pl[4];
            cvt_hl(sacc[2*kk][0],   sacc[2*kk][1],   ph[0], pl[0]);
            cvt_hl(sacc[2*kk][2],   sacc[2*kk][3],   ph[1], pl[1]);
            cvt_hl(sacc[2*kk+1][0], sacc[2*kk+1][1], ph[2], pl[2]);
            cvt_hl(sacc[2*kk+1][2], sacc[2*kk+1][3], ph[3], pl[3]);
            #pragma unroll
            for (int nd = 0; nd < 8; nd++) {
                uint32_t vh[2], vl[2];
                int off = (nd * 8 + g) * FA_SK + kk * 8 + tg;
                vh[0] = vhw[off]; vh[1] = vhw[off + 4];
                vl[0] = vlw[off]; vl[1] = vlw[off + 4];
                mma_bf16(oacc[nd], ph, vh);
                mma_bf16(oacc[nd], ph, vl);
                mma_bf16(oacc[nd], pl, vh);
            }
        }
        __syncthreads();
    }

    float il0 = 1.0f / l0, il1 = 1.0f / l1;
    float* Ob = Og + ((size_t)nh * LTOK + q0) * HD;
    #pragma unroll
    for (int nd = 0; nd < 8; nd++) {
        int col = nd * 8 + tg * 2;
        *reinterpret_cast<float2*>(&Ob[(size_t)row0 * HD + col]) =
            make_float2(oacc[nd][0] * il0, oacc[nd][1] * il0);
        *reinterpret_cast<float2*>(&Ob[(size_t)(row0 + 8) * HD + col]) =
            make_float2(oacc[nd][2] * il1, oacc[nd][3] * il1);
    }
}

// ---------------- output apply (separate, as in R13) ----------------
__global__ void k_apply_out(const float* __restrict__ O, const float* __restrict__ Mi,
                            uint32_t* __restrict__ omh, uint32_t* __restrict__ oml) {
    int idx = blockIdx.x * blockDim.x + threadIdx.x;
    if (idx >= NAPP) return;
    int g = idx & 15, h = (idx >> 4) & 3, t = (idx >> 6) & (LTOK-1), n = idx >> 16;
    const float* M = Mi + ((size_t)(n*LTOK + t))*16;
    const float* s = O + (((size_t)(n*NH + h))*LTOK + t)*HD + g*4;
    float x0=s[0], x1=s[1], x2=s[2], x3=s[3];
    float d[4];
    #pragma unroll
    for (int i = 0; i < 4; i++)
        d[i] = M[i*4+0]*x0 + M[i*4+1]*x1 + M[i*4+2]*x2 + M[i*4+3]*x3;
    size_t w = (((size_t)(n*LTOK + t))*CC + h*HD + g*4) >> 1;
    uint32_t h0, l0, h1, l1;
    cvt_hl(d[0], d[1], h0, l0);
    cvt_hl(d[2], d[3], h1, l1);
    omh[w] = h0;   oml[w] = l0;
    omh[w+1] = h1; oml[w+1] = l1;
}

// ---------------- layout kernels ----------------
__global__ void k_build_x(const float* __restrict__ f, float* __restrict__ x,
                          uint32_t* __restrict__ xh, uint32_t* __restrict__ xl,
                          uint32_t* __restrict__ xph, uint32_t* __restrict__ xpl) {
    int idx = blockIdx.x * blockDim.x + threadIdx.x;
    if (idx >= XW) return;
    int c2 = idx & 127;
    int l  = (idx >> 7) & (LTOK-1);
    int n  = idx >> 17;
    int c  = c2 * 2;
    float a = f[((size_t)n*CC + c)*LTOK + l];
    float b = f[((size_t)n*CC + c + 1)*LTOK + l];
    reinterpret_cast<float2*>(x)[idx] = make_float2(a, b);
    uint32_t h, lw;
    cvt_hl(a, b, h, lw);
    xh[idx] = h; xl[idx] = lw;
    xph[idx] = h; xpl[idx] = lw;
}

__global__ void k_final(const float* __restrict__ x, float* __restrict__ o) {
    int idx = blockIdx.x * blockDim.x + threadIdx.x;
    if (idx >= ROWS_*CC) return;
    int l = idx & (LTOK-1);
    int c = (idx >> 10) & (CC-1);
    int n = idx >> 18;
    o[idx] = x[((size_t)n*LTOK + l)*CC + c];
}

// ---------------- PRoPE matrix build ----------------
__device__ __forceinline__ void prope_forward(const float* vm, const float* Kc,
                                              float u, float vyy, float* M) {
    float fx = Kc[0] * (1.0f/128.0f), fy = Kc[4] * (1.0f/128.0f);
    float cx = Kc[2] * (1.0f/128.0f), cy = Kc[5] * (1.0f/128.0f);
    float a = cx - u, b = cy - vyy;
    #pragma unroll
    for (int c = 0; c < 4; c++) {
        M[0*4+c] = fx*vm[0*4+c] + a*vm[2*4+c];
        M[1*4+c] = fy*vm[1*4+c] + b*vm[2*4+c];
        M[2*4+c] = vm[2*4+c];
        M[3*4+c] = vm[3*4+c];
    }
}

__global__ void k_prope_q(const float* __restrict__ vms, const float* __restrict__ Ks,
                          float* __restrict__ Mq, float* __restrict__ Mqi) {
    int idx = blockIdx.x * blockDim.x + threadIdx.x;
    if (idx >= NVB*LTOK) return;
    int n = idx >> 10, t = idx & (LTOK-1);
    int px = t & 31, py = t >> 5;
    float u  = (px + 0.5f) * (1.0f/32.0f);
    float vy = (py + 0.5f) * (1.0f/32.0f);
    const float* vm = vms + n*16;
    const float* Kc = Ks + n*9;
    float M[16];
    prope_forward(vm, Kc, u, vy, M);
    #pragma unroll
    for (int i = 0; i < 16; i++) Mq[idx*16+i] = M[i];

    float r00=vm[0],r01=vm[1],r02=vm[2],  t0=vm[3];
    float r10=vm[4],r11=vm[5],r12=vm[6],  t1=vm[7];
    float r20=vm[8],r21=vm[9],r22=vm[10], t2=vm[11];
    float det = r00*(r11*r22-r12*r21) - r01*(r10*r22-r12*r20) + r02*(r10*r21-r11*r20);
    float id = 1.0f/det;
    float Ri[9];
    Ri[0]=(r11*r22-r12*r21)*id; Ri[1]=(r02*r21-r01*r22)*id; Ri[2]=(r01*r12-r02*r11)*id;
    Ri[3]=(r12*r20-r10*r22)*id; Ri[4]=(r00*r22-r02*r20)*id; Ri[5]=(r02*r10-r00*r12)*id;
    Ri[6]=(r10*r21-r11*r20)*id; Ri[7]=(r01*r20-r00*r21)*id; Ri[8]=(r00*r11-r01*r10)*id;
    float ti0 = -(Ri[0]*t0 + Ri[1]*t1 + Ri[2]*t2);
    float ti1 = -(Ri[3]*t0 + Ri[4]*t1 + Ri[5]*t2);
    float ti2 = -(Ri[6]*t0 + Ri[7]*t1 + Ri[8]*t2);
    float fx = Kc[0]*(1.0f/128.0f), fy = Kc[4]*(1.0f/128.0f);
    float cx = Kc[2]*(1.0f/128.0f), cy = Kc[5]*(1.0f/128.0f);
    float a = cx - u, b = cy - vy;
    float ifx = 1.0f/fx, ify = 1.0f/fy;
    float Mi[16];
    float tv[3] = {ti0, ti1, ti2};
    #pragma unroll
    for (int i = 0; i < 3; i++) {
        Mi[i*4+0] = Ri[i*3+0]*ifx;
        Mi[i*4+1] = Ri[i*3+1]*ify;
        Mi[i*4+2] = -Ri[i*3+0]*a*ifx - Ri[i*3+1]*b*ify + Ri[i*3+2];
        Mi[i*4+3] = tv[i];
    }
    Mi[12]=0.f; Mi[13]=0.f; Mi[14]=0.f; Mi[15]=1.f;
    #pragma unroll
    for (int i = 0; i < 16; i++) Mqi[idx*16+i] = Mi[i];
}

__global__ void k_prope_kv(const float* __restrict__ vms, const float* __restrict__ Ks,
                           float* __restrict__ Mkv) {
    int idx = blockIdx.x * blockDim.x + threadIdx.x;
    if (idx >= NVB*TKX) return;
    int n = idx >> 11, tt = idx & (TKX-1);
    int m = tt >> 10, l = tt & (LTOK-1);
    int vvi = n >> 1, b = n & 1;
    int j = m + (m >= vvi ? 1 : 0);
    int cam = j*BB + b;
    int px = l & 31, py = l >> 5;
    float u  = (px + 0.5f)*(1.0f/32.0f);
    float vy = (py + 0.5f)*(1.0f/32.0f);
    float M[16];
    prope_forward(vms + cam*16, Ks + cam*9, u, vy, M);
    #pragma unroll
    for (int i = 0; i < 16; i++) Mkv[idx*16+i] = M[i];
}

// ---------------- fused per-token applies (packed Q/K/V outputs) -------------
__global__ void k_apply_all(const float* __restrict__ qkv, int stride,
                            const float* __restrict__ Mqi, const float* __restrict__ Mats,
                            uint32_t* __restrict__ qph, uint32_t* __restrict__ qpl,
                            uint32_t* __restrict__ kph, uint32_t* __restrict__ kpl,
                            uint32_t* __restrict__ vph, uint32_t* __restrict__ vpl,
                            int Tk, int gather, int nkv)
{
    int idx = blockIdx.x * blockDim.x + threadIdx.x;
    if (idx < NAPP) {
        int g = idx & 15, h = (idx >> 4) & 3, t = (idx >> 6) & (LTOK-1), n = idx >> 16;
        const float* M = Mqi + ((size_t)(n*LTOK + t))*16;
        const float* s = qkv + ((size_t)(n*LTOK + t))*stride + h*HD + g*4;
        float x0=s[0], x1=s[1], x2=s[2], x3=s[3];
        float d[4];
        #pragma unroll
        for (int i = 0; i < 4; i++)
            d[i] = M[0*4+i]*x0 + M[1*4+i]*x1 + M[2*4+i]*x2 + M[3*4+i]*x3;
        uint32_t h0, l0, h1, l1;
        cvt_hl(d[0]*0.125f, d[1]*0.125f, h0, l0);
        cvt_hl(d[2]*0.125f, d[3]*0.125f, h1, l1);
        size_t wb = (((size_t)(n*NH + h))*LTOK + t)*32 + g*2;
        qph[wb] = h0;   qpl[wb] = l0;
        qph[wb+1] = h1; qpl[wb+1] = l1;
    } else if (idx < NAPP + nkv) {
        int i2 = idx - NAPP;
        int g = i2 & 15, h = (i2 >> 4) & 3;
        int tt = (i2 >> 6) % Tk, n = (i2 >> 6) / Tk;
        size_t srcRow;
        if (gather) {
            int m = tt >> 10, l = tt & (LTOK-1);
            int vvi = n >> 1, b = n & 1;
            int j = m + (m >= vvi ? 1 : 0);
            srcRow = (size_t)(j*BB + b)*LTOK + l;
        } else {
            srcRow = (size_t)n*LTOK + tt;
        }
        const float* M = Mats + ((size_t)n*Tk + tt)*16;
        const float* s = qkv + srcRow*stride + 256 + h*HD + g*4;
        float x0=s[0], x1=s[1], x2=s[2], x3=s[3];
        float d[4];
        #pragma unroll
        for (int i = 0; i < 4; i++)
            d[i] = M[i*4+0]*x0 + M[i*4+1]*x1 + M[i*4+2]*x2 + M[i*4+3]*x3;
        size_t wb = (((size_t)(n*NH + h))*Tk + tt)*32 + g*2;
        uint32_t h0, l0, h1, l1;
        cvt_hl(d[0], d[1], h0, l0);
        cvt_hl(d[2], d[3], h1, l1);
        kph[wb] = h0;   kpl[wb] = l0;
        kph[wb+1] = h1; kpl[wb+1] = l1;
    } else if (idx < NAPP + 2*nkv) {
        int i2 = idx - NAPP - nkv;
        int tt = i2 % Tk;
        int rest = i2 / Tk;
        int g = rest & 15, h = (rest >> 4) & 3, n = rest >> 6;
        size_t srcRow;
        if (gather) {
            int m = tt >> 10, l = tt & (LTOK-1);
            int vvi = n >> 1, b = n & 1;
            int j = m + (m >= vvi ? 1 : 0);
            srcRow = (size_t)(j*BB + b)*LTOK + l;
        } else {
            srcRow = (size_t)n*LTOK + tt;
        }
        const float* M = Mats + ((size_t)n*Tk + tt)*16;
        const float* s = qkv + srcRow*stride + 512 + h*HD + g*4;
        float x0=s[0], x1=s[1], x2=s[2], x3=s[3];
        #pragma unroll
        for (int i = 0; i < 4; i++) {
            float v = M[i*4+0]*x0 + M[i*4+1]*x1 + M[i*4+2]*x2 + M[i*4+3]*x3;
            float vn = __shfl_down_sync(0xffffffff, v, 1);
            if ((tt & 1) == 0) {
                uint32_t hh2, ll2;
                cvt_hl(v, vn, hh2, ll2);
                size_t wb = ((size_t)(n*NH + h)*HD + g*4 + i)*(Tk >> 1) + (tt >> 1);
                vph[wb] = hh2; vpl[wb] = ll2;
            }
        }
    }
}

// ---------------- layernorm: sums nparts partials, optional bf16 + cat writes --
__global__ void k_ln(float* __restrict__ dst, const float* __restrict__ parts, int nparts,
                     const float* __restrict__ w, const float* __restrict__ b, int add,
                     uint32_t* __restrict__ oh, uint32_t* __restrict__ ol,
                     uint32_t* __restrict__ oh2, uint32_t* __restrict__ ol2,
                     uint32_t* __restrict__ ch, uint32_t* __restrict__ cl, int catHalf) {
    __shared__ float red[256];
    int row = blockIdx.x, tid = threadIdx.x;
    float v = parts[(size_t)row*CC + tid];
    for (int p = 1; p < nparts; p++)
        v += parts[(size_t)p*ROWS_*CC + (size_t)row*CC + tid];
    red[tid] = v; __syncthreads();
    for (int s = 128; s > 0; s >>= 1) { if (tid < s) red[tid] += red[tid+s]; __syncthreads(); }
    float mu = red[0] * (1.0f/CC); __syncthreads();
    float d = v - mu;
    red[tid] = d * d; __syncthreads();
    for (int s = 128; s > 0; s >>= 1) { if (tid < s) red[tid] += red[tid+s]; __syncthreads(); }
    float var = red[0] * (1.0f/CC);
    float o = d * rsqrtf(var + 1e-5f) * w[tid] + b[tid];
    float fin;
    if (add) { fin = dst[(size_t)row*CC + tid] + o; dst[(size_t)row*CC + tid] = fin; }
    else     { fin = o; dst[(size_t)row*CC + tid] = fin; }
    if (oh || ch) {
        __syncthreads();
        red[tid] = fin;
        __syncthreads();
        if (tid < 128) {
            uint32_t h, l;
            cvt_hl(red[2*tid], red[2*tid+1], h, l);
            if (oh) {
                oh[(size_t)row*(CC/2) + tid] = h;
                ol[(size_t)row*(CC/2) + tid] = l;
                if (oh2) {
                    oh2[(size_t)row*(CC/2) + tid] = h;
                    ol2[(size_t)row*(CC/2) + tid] = l;
                }
            }
            if (ch) {
                size_t cw = (size_t)row*(FFNI/2) + catHalf*128 + tid;
                ch[cw] = h; cl[cw] = l;
            }
        }
    }
}

// ---------------- host driver ----------------
static const int GSMEM128 = 98304;
static const int GSMEM64  = 73728;

static void gemm128(const uint32_t* Ah, const uint32_t* Al,
                    const uint32_t* A2h, const uint32_t* A2l, int nsplit,
                    const uint32_t* Bh, const uint32_t* Bl,
                    float* C, int M, int N, int K) {
    dim3 g(N/128, M/128, 1);
    tc_gemm<128,0><<<g, 256, GSMEM128>>>(Ah, Al, A2h, A2l, nsplit, Bh, Bl,
                                         C, nullptr, nullptr, M, N, K, K);
}
static void gemm64s(const uint32_t* Ah, const uint32_t* Al,
                    const uint32_t* Bh, const uint32_t* Bl,
                    float* C, int M, int N, int Ktot, int nz) {
    dim3 g(N/64, M/128, nz);
    tc_gemm<64,0><<<g, 256, GSMEM64>>>(Ah, Al, Ah, Al, 1<<30, Bh, Bl,
                                       C, nullptr, nullptr, M, N, Ktot/nz, Ktot);
}
static void gemm_gelu_hl(const uint32_t* Ah, const uint32_t* Al,
                         const uint32_t* Bh, const uint32_t* Bl,
                         uint32_t* Oh, uint32_t* Ol, int M, int N, int K) {
    dim3 g(N/128, M/128, 1);
    tc_gemm<128,1><<<g, 256, GSMEM128>>>(Ah, Al, Ah, Al, 1<<30, Bh, Bl,
                                         nullptr, Oh, Ol, M, N, K, K);
}

extern "C" void kernel_launch(void* const* d_in, const int* in_sizes, int n_in,
                              void* d_out, int out_size) {
    const float* feats = (const float*)d_in[0];
    const float* vms   = (const float*)d_in[1];
    const float* Ks    = (const float*)d_in[2];
    const float* Wq    = (const float*)d_in[3];
    const float* Wk    = (const float*)d_in[4];
    const float* Wv    = (const float*)d_in[5];
    const float* Wm    = (const float*)d_in[6];
    const float* n1w   = (const float*)d_in[7];
    const float* n1b   = (const float*)d_in[8];
    const float* W1    = (const float*)d_in[9];
    const float* W2    = (const float*)d_in[10];
    const float* n2w   = (const float*)d_in[11];
    const float* n2b   = (const float*)d_in[12];

    cudaFuncSetAttribute(tc_gemm<128,0>, cudaFuncAttributeMaxDynamicSharedMemorySize, GSMEM128);
    cudaFuncSetAttribute(tc_gemm<128,1>, cudaFuncAttributeMaxDynamicSharedMemorySize, GSMEM128);
    cudaFuncSetAttribute(tc_gemm<64,0>,  cudaFuncAttributeMaxDynamicSharedMemorySize, GSMEM64);

    void* p;
    float *x,*qkv,*O,*msg,*msg2,*h22,*Mq,*Mqi,*Mkv;
    uint32_t *qph,*qpl,*kph,*kpl,*vph,*vpl;
    uint32_t *xh,*xl,*xpreh,*xprel,*omh,*oml,*cath,*catl,*hh,*hl,*wh,*wl;
    cudaGetSymbolAddress(&p, g_x);    x   = (float*)p;
    cudaGetSymbolAddress(&p, g_qkv);  qkv = (float*)p;
    cudaGetSymbolAddress(&p, g_qph);  qph = (uint32_t*)p;
    cudaGetSymbolAddress(&p, g_qpl);  qpl = (uint32_t*)p;
    cudaGetSymbolAddress(&p, g_kph);  kph = (uint32_t*)p;
    cudaGetSymbolAddress(&p, g_kpl);  kpl = (uint32_t*)p;
    cudaGetSymbolAddress(&p, g_vph);  vph = (uint32_t*)p;
    cudaGetSymbolAddress(&p, g_vpl);  vpl = (uint32_t*)p;
    cudaGetSymbolAddress(&p, g_O);    O   = (float*)p;
    cudaGetSymbolAddress(&p, g_msg);  msg = (float*)p;
    cudaGetSymbolAddress(&p, g_msg2); msg2= (float*)p;
    cudaGetSymbolAddress(&p, g_h22);  h22 = (float*)p;
    cudaGetSymbolAddress(&p, g_Mq);   Mq  = (float*)p;
    cudaGetSymbolAddress(&p, g_Mqi);  Mqi = (float*)p;
    cudaGetSymbolAddress(&p, g_Mkv);  Mkv = (float*)p;
    cudaGetSymbolAddress(&p, g_xh);    xh    = (uint32_t*)p;
    cudaGetSymbolAddress(&p, g_xl);    xl    = (uint32_t*)p;
    cudaGetSymbolAddress(&p, g_xpreh); xpreh = (uint32_t*)p;
    cudaGetSymbolAddress(&p, g_xprel); xprel = (uint32_t*)p;
    cudaGetSymbolAddress(&p, g_omh);   omh   = (uint32_t*)p;
    cudaGetSymbolAddress(&p, g_oml);   oml   = (uint32_t*)p;
    cudaGetSymbolAddress(&p, g_cath);  cath  = (uint32_t*)p;
    cudaGetSymbolAddress(&p, g_catl);  catl  = (uint32_t*)p;
    cudaGetSymbolAddress(&p, g_hh);    hh    = (uint32_t*)p;
    cudaGetSymbolAddress(&p, g_hl);    hl    = (uint32_t*)p;
    cudaGetSymbolAddress(&p, g_wh);    wh    = (uint32_t*)p;
    cudaGetSymbolAddress(&p, g_wl);    wl    = (uint32_t*)p;

    const int ROWS = ROWS_;
    const int NEL  = ROWS * CC;
    const int NKV_SELF  = NAPP;
    const int NKV_CROSS = NVB*TKX*NH*16;

    k_cvt_all<<<WTOT/256, 256>>>(Wq, Wk, Wv, Wm, W1, W2, wh, wl);
    k_build_x<<<(XW+255)/256, 256>>>(feats, x, xh, xl, xpreh, xprel);
    k_prope_q<<<(ROWS+255)/256, 256>>>(vms, Ks, Mq, Mqi);
    k_prope_kv<<<(NVB*TKX+255)/256, 256>>>(vms, Ks, Mkv);

    for (int ly = 0; ly < 2; ly++) {
        // ---------- self attention ----------
        gemm128(xh, xl, xh, xl, 1<<30,
                wh + WQKV0 + (ly*2+0)*98304, wl + WQKV0 + (ly*2+0)*98304,
                qkv, ROWS, 768, CC);
        k_apply_all<<<(NAPP + 2*NKV_SELF)/256, 256>>>(
            qkv, 768, Mqi, Mq, qph, qpl, kph, kpl, vph, vpl, LTOK, 0, NKV_SELF);
        k_flash<<<dim3(LTOK/128, NVB*NH), 256>>>(qph, qpl, kph, kpl, vph, vpl, O, LTOK);
        k_apply_out<<<NAPP/256, 256>>>(O, Mqi, omh, oml);
        gemm64s(omh, oml, wh + WMO + (ly*2+0)*32768, wl + WMO + (ly*2+0)*32768,
                msg2, ROWS, CC, CC, 2);
        k_ln<<<ROWS, 256>>>(x, msg2, 2, n1w + (ly*2+0)*CC, n1b + (ly*2+0)*CC, 1,
                            xh, xl, nullptr, nullptr, cath, catl, 0);

        // ---------- cross attention ----------
        gemm128(xh, xl, xpreh, xprel, 256,
                wh + WQKV0 + (ly*2+1)*98304, wl + WQKV0 + (ly*2+1)*98304,
                qkv, ROWS, 768, CC);
        k_apply_all<<<(NAPP + 2*NKV_CROSS)/256, 256>>>(
            qkv, 768, Mqi, Mkv, qph, qpl, kph, kpl, vph, vpl, TKX, 1, NKV_CROSS);
        k_flash<<<dim3(LTOK/128, NVB*NH), 256>>>(qph, qpl, kph, kpl, vph, vpl, O, TKX);
        k_apply_out<<<NAPP/256, 256>>>(O, Mqi, omh, oml);
        gemm64s(omh, oml, wh + WMO + (ly*2+1)*32768, wl + WMO + (ly*2+1)*32768,
                msg2, ROWS, CC, CC, 2);
        k_ln<<<ROWS, 256>>>(msg, msg2, 2, n1w + (ly*2+1)*CC, n1b + (ly*2+1)*CC, 0,
                            nullptr, nullptr, nullptr, nullptr, cath, catl, 1);

        // ---------- FFN ----------
        gemm_gelu_hl(cath, catl,
                     wh + W1O + (size_t)ly*524288, wl + W1O + (size_t)ly*524288,
                     hh, hl, ROWS, FFNH, FFNI);
        gemm64s(hh, hl, wh + W2O + (size_t)ly*262144, wl + W2O + (size_t)ly*262144,
                h22, ROWS, CC, FFNH, 4);
        k_ln<<<ROWS, 256>>>(x, h22, 4, n2w + ly*CC, n2b + ly*CC, 1,
                            xh, xl, xpreh, xprel, nullptr, nullptr, 0);
    }

    k_final<<<(NEL+255)/256, 256>>>(x, (float*)d_out);
}

// round 16
// speedup vs baseline: 1.0314x; 1.0238x over previous
#include <cuda_runtime.h>
#include <cuda_bf16.h>
#include <math.h>
#include <stdint.h>

// ---------------- problem constants ----------------
#define NVB   6
#define VV    3
#define BB    2
#define CC    256
#define LTOK  1024
#define TKX   2048
#define NH    4
#define HD    64
#define FFNI  512
#define FFNH  2048

#define ROWS_ (NVB*LTOK)          // 6144
#define XW    (NVB*LTOK*CC/2)
#define NAPP  (NVB*LTOK*NH*16)    // 393216

// ---------------- device scratch ----------------
__device__ float g_x   [ROWS_*CC];
__device__ float g_qkv [ROWS_*768];
__device__ uint32_t g_qph[NVB*NH*LTOK*32], g_qpl[NVB*NH*LTOK*32];
__device__ uint32_t g_kph[NVB*NH*LTOK*32], g_kpl[NVB*NH*LTOK*32];   // per-CAM K
__device__ uint32_t g_vph[NVB*NH*LTOK*32], g_vpl[NVB*NH*LTOK*32];   // per-CAM V^T
__device__ float g_O   [NVB*NH*LTOK*HD];
__device__ float g_msg [ROWS_*CC];
__device__ float g_msg2[2*ROWS_*CC];
__device__ float g_h22 [4*ROWS_*CC];
__device__ float g_Mq  [NVB*LTOK*16];
__device__ float g_Mqi [NVB*LTOK*16];

__device__ uint32_t g_xh   [XW],  g_xl   [XW];
__device__ uint32_t g_xpreh[XW],  g_xprel[XW];
__device__ uint32_t g_omh  [XW],  g_oml  [XW];
__device__ uint32_t g_cath [ROWS_*FFNI/2], g_catl[ROWS_*FFNI/2];
__device__ uint32_t g_hh   [ROWS_*FFNH/2], g_hl  [ROWS_*FFNH/2];
#define WQKV0 0
#define WMO   393216
#define W1O   524288
#define W2O   1572864
#define WTOT  2097152
__device__ uint32_t g_wh[WTOT], g_wl[WTOT];

// ---------------- helpers ----------------
__device__ __forceinline__ void cvt_hl(float x, float y, uint32_t& hi, uint32_t& lo) {
    __nv_bfloat162 h = __floats2bfloat162_rn(x, y);
    float rx = x - __bfloat162float(h.x);
    float ry = y - __bfloat162float(h.y);
    __nv_bfloat162 l = __floats2bfloat162_rn(rx, ry);
    hi = *reinterpret_cast<uint32_t*>(&h);
    lo = *reinterpret_cast<uint32_t*>(&l);
}

__device__ __forceinline__ void mma_bf16(float* c, const uint32_t* a, const uint32_t* b) {
    asm volatile(
        "mma.sync.aligned.m16n8k16.row.col.f32.bf16.bf16.f32 "
        "{%0,%1,%2,%3}, {%4,%5,%6,%7}, {%8,%9}, {%0,%1,%2,%3};"
        : "+f"(c[0]), "+f"(c[1]), "+f"(c[2]), "+f"(c[3])
        : "r"(a[0]), "r"(a[1]), "r"(a[2]), "r"(a[3]), "r"(b[0]), "r"(b[1]));
}

__device__ __forceinline__ void ldsm4(uint32_t* r, uint32_t addr) {
    asm volatile("ldmatrix.sync.aligned.m8n8.x4.shared.b16 {%0,%1,%2,%3}, [%4];"
        : "=r"(r[0]), "=r"(r[1]), "=r"(r[2]), "=r"(r[3]) : "r"(addr));
}

__device__ __forceinline__ uint32_t smem_u32(const void* p) {
    uint32_t a;
    asm("{ .reg .u64 t; cvta.to.shared.u64 t, %1; cvt.u32.u64 %0, t; }" : "=r"(a) : "l"(p));
    return a;
}

__device__ __forceinline__ void cp16(uint32_t smem, const void* g) {
    asm volatile("cp.async.cg.shared.global [%0], [%1], 16;" :: "r"(smem), "l"(g));
}
#define CP_COMMIT() asm volatile("cp.async.commit_group;")
#define CP_WAIT(N)  asm volatile("cp.async.wait_group %0;" :: "n"(N))

// ---------------- all-weight conversion + QKV repack ----------------
__global__ void k_cvt_all(const float* __restrict__ Wq, const float* __restrict__ Wk,
                          const float* __restrict__ Wv, const float* __restrict__ Wm,
                          const float* __restrict__ W1, const float* __restrict__ W2,
                          uint32_t* __restrict__ wh, uint32_t* __restrict__ wl) {
    int i = blockIdx.x * blockDim.x + threadIdx.x;
    if (i >= WTOT) return;
    const float* src;
    if (i < WMO) {
        int lyp  = i / 98304;
        int sub  = i % 98304;
        int which = sub / 32768;
        int woff  = sub % 32768;
        const float* base = (which == 0) ? Wq : (which == 1) ? Wk : Wv;
        src = base + (size_t)lyp * 65536 + (size_t)woff * 2;
    } else if (i < W1O) {
        src = Wm + (size_t)(i - WMO) * 2;
    } else if (i < W2O) {
        src = W1 + (size_t)(i - W1O) * 2;
    } else {
        src = W2 + (size_t)(i - W2O) * 2;
    }
    float2 v = *reinterpret_cast<const float2*>(src);
    uint32_t h, l;
    cvt_hl(v.x, v.y, h, l);
    wh[i] = h; wl[i] = l;
}

// ---------------- tensor-core bf16x3 GEMM (BN template, split-K via z) -------
template<int BN, int OUT>
__global__ __launch_bounds__(256)
void tc_gemm(const uint32_t* __restrict__ Ah, const uint32_t* __restrict__ Al,
             const uint32_t* __restrict__ A2h, const uint32_t* __restrict__ A2l,
             int nsplit,
             const uint32_t* __restrict__ Bh, const uint32_t* __restrict__ Bl,
             float* __restrict__ C, uint32_t* __restrict__ Oh, uint32_t* __restrict__ Ol,
             int M, int N, int K, int Krow)
{
    constexpr int WARPS_N = BN / 32;
    constexpr int WMX = 128 / (8 / WARPS_N);
    constexpr int MT = WMX / 16;
    constexpr int B_HI = BN * 48;
    constexpr int STAGE = 12288 + 2 * B_HI;

    extern __shared__ uint32_t smem[];
    const uint32_t sb0 = smem_u32(smem);

    const int m0 = blockIdx.y * 128;
    const int n0 = blockIdx.x * BN;
    const int kz = blockIdx.z;
    const int tid = threadIdx.x;
    const int wid = tid >> 5, lane = tid & 31;
    const int g = lane >> 2, tg = lane & 3;
    const int warp_m = wid / WARPS_N, warp_n = wid % WARPS_N;
    const int wm0 = warp_m * WMX, wn0 = warp_n * 32;
    const int Krow2 = Krow >> 1;
    const size_t kzoff = (size_t)kz * (K >> 1);

    const int rowa = tid >> 1, hw = (tid & 1) * 4;

    const int a_lrow = lane & 15;
    const int a_lcol = (lane >> 4) * 4;
    const int b_lrow = (lane & 7) + ((lane >> 4) << 3);
    const int b_lcol = ((lane >> 3) & 1) * 4;

    float acc[MT][4][4];
    #pragma unroll
    for (int i = 0; i < MT; i++)
        #pragma unroll
        for (int j = 0; j < 4; j++)
            #pragma unroll
            for (int r = 0; r < 4; r++) acc[i][j][r] = 0.f;

    const bool useA2 = (n0 >= nsplit);
    const uint32_t* Ab  = (useA2 ? A2h : Ah) + (size_t)(m0 + rowa) * Krow2 + hw + kzoff;
    const uint32_t* Alb = (useA2 ? A2l : Al) + (size_t)(m0 + rowa) * Krow2 + hw + kzoff;
    const uint32_t* Bb  = Bh + (size_t)(n0 + rowa) * Krow2 + hw + kzoff;
    const uint32_t* Blb = Bl + (size_t)(n0 + rowa) * Krow2 + hw + kzoff;
    C += (size_t)kz * M * N;

    const uint32_t dst_off = (uint32_t)(rowa * 12 + hw) * 4;
    const int nk = K >> 4;

    #define ISSUE(tile, stage) do {                                   \
        uint32_t sb = sb0 + (stage) * (uint32_t)STAGE;                \
        int ko = (tile) * 8;                                          \
        cp16(sb + dst_off,        Ab + ko);                           \
        cp16(sb + 6144 + dst_off, Alb + ko);                          \
        if (BN == 128 || tid < 128) {                                 \
            cp16(sb + 12288 + dst_off,        Bb + ko);               \
            cp16(sb + 12288 + B_HI + dst_off, Blb + ko);              \
        }                                                             \
    } while (0)

    #pragma unroll
    for (int s = 0; s < 3; s++) {
        if (s < nk) ISSUE(s, s);
        CP_COMMIT();
    }

    for (int kt = 0; kt < nk; kt++) {
        if (kt + 3 < nk) ISSUE(kt + 3, (kt + 3) & 3);
        CP_COMMIT();
        CP_WAIT(3);
        __syncthreads();

        const uint32_t sb = sb0 + (kt & 3) * (uint32_t)STAGE;
        uint32_t ah[MT][4], al[MT][4], bh2[4][2], bl2[4][2];
        #pragma unroll
        for (int mi = 0; mi < MT; mi++) {
            uint32_t woff = (uint32_t)((wm0 + mi*16 + a_lrow) * 12 + a_lcol) * 4;
            ldsm4(ah[mi], sb + woff);
            ldsm4(al[mi], sb + 6144 + woff);
        }
        #pragma unroll
        for (int p = 0; p < 2; p++) {
            uint32_t woff = (uint32_t)((wn0 + p*16 + b_lrow) * 12 + b_lcol) * 4;
            uint32_t r[4];
            ldsm4(r, sb + 12288 + woff);
            bh2[2*p][0] = r[0]; bh2[2*p][1] = r[1];
            bh2[2*p+1][0] = r[2]; bh2[2*p+1][1] = r[3];
            ldsm4(r, sb + 12288 + B_HI + woff);
            bl2[2*p][0] = r[0]; bl2[2*p][1] = r[1];
            bl2[2*p+1][0] = r[2]; bl2[2*p+1][1] = r[3];
        }
        #pragma unroll
        for (int mi = 0; mi < MT; mi++)
            #pragma unroll
            for (int ni = 0; ni < 4; ni++) {
                mma_bf16(acc[mi][ni], ah[mi], bh2[ni]);
                mma_bf16(acc[mi][ni], ah[mi], bl2[ni]);
                mma_bf16(acc[mi][ni], al[mi], bh2[ni]);
            }
        __syncthreads();
    }
    #undef ISSUE

    #pragma unroll
    for (int mi = 0; mi < MT; mi++) {
        #pragma unroll
        for (int ni = 0; ni < 4; ni++) {
            long long row0 = m0 + wm0 + mi * 16 + g;
            int col = n0 + wn0 + ni * 8 + tg * 2;
            if (OUT == 0) {
                *reinterpret_cast<float2*>(&C[row0 * N + col]) =
                    make_float2(acc[mi][ni][0], acc[mi][ni][1]);
                *reinterpret_cast<float2*>(&C[(row0 + 8) * N + col]) =
                    make_float2(acc[mi][ni][2], acc[mi][ni][3]);
            } else {
                float r[4];
                #pragma unroll
                for (int t = 0; t < 4; t++) {
                    float v = acc[mi][ni][t];
                    r[t] = 0.5f * v * (1.0f + erff(v * 0.70710678118654752f));
                }
                uint32_t h0, l0, h1, l1;
                cvt_hl(r[0], r[1], h0, l0);
                cvt_hl(r[2], r[3], h1, l1);
                size_t w0 = (size_t)(row0 * N + col) >> 1;
                size_t w1 = (size_t)((row0 + 8) * N + col) >> 1;
                Oh[w0] = h0; Ol[w0] = l0;
                Oh[w1] = h1; Ol[w1] = l1;
            }
        }
    }
}

// ---------------- fused flash attention (per-camera K/V, fp32 O out) ---------
// K/V are stored per CAMERA: kp[cam][h][l][32w], vpT[cam][h][d][l/2].
// Self: Tk=LTOK, cam = query seq. Cross: Tk=2*LTOK, chunk m -> cam=j*BB+b, j=m+(m>=v).
#define FA_SK 36
__global__ __launch_bounds__(256)
void k_flash(const uint32_t* __restrict__ qph, const uint32_t* __restrict__ qpl,
             const uint32_t* __restrict__ kph, const uint32_t* __restrict__ kpl,
             const uint32_t* __restrict__ vph, const uint32_t* __restrict__ vpl,
             float* __restrict__ Og, int Tk)
{
    __shared__ uint32_t khw[64*FA_SK], klw[64*FA_SK];
    __shared__ uint32_t vhw[64*FA_SK], vlw[64*FA_SK];

    const int nh = blockIdx.y;
    const int q0 = blockIdx.x * 128;
    const int tid = threadIdx.x, wid = tid >> 5, lane = tid & 31;
    const int g = lane >> 2, tg = lane & 3;

    const int nq = nh / NH, hq = nh % NH;
    const int vq = nq >> 1, bq = nq & 1;

    const uint32_t* Qh = qph + ((size_t)nh * LTOK + q0) * 32;
    const uint32_t* Ql = qpl + ((size_t)nh * LTOK + q0) * 32;

    const int row0 = wid * 16 + g;
    uint32_t qh[4][4], ql[4][4];
    #pragma unroll
    for (int kk = 0; kk < 4; kk++) {
        int w0 = row0 * 32 + kk * 8 + tg;
        int w1 = (row0 + 8) * 32 + kk * 8 + tg;
        qh[kk][0] = Qh[w0];     ql[kk][0] = Ql[w0];
        qh[kk][1] = Qh[w1];     ql[kk][1] = Ql[w1];
        qh[kk][2] = Qh[w0 + 4]; ql[kk][2] = Ql[w0 + 4];
        qh[kk][3] = Qh[w1 + 4]; ql[kk][3] = Ql[w1 + 4];
    }

    float m0 = -1e30f, m1 = -1e30f, l0 = 0.f, l1 = 0.f;
    float oacc[8][4];
    #pragma unroll
    for (int i = 0; i < 8; i++)
        #pragma unroll
        for (int t = 0; t < 4; t++) oacc[i][t] = 0.f;

    const int r = tid >> 2, c2 = (tid & 3) * 8;
    uint4 kh0, kh1, kl0, kl1, vh0, vh1, vl0, vl1;

    #define CAM_OF(kv) ((Tk == LTOK) ? nq : \
        ((((kv) >> 10) + (((kv) >> 10) >= vq ? 1 : 0)) * BB + bq))
    #define LOADKV(camv, l0v) do {                                                    \
        size_t kb = (((size_t)((camv)*NH + hq))*LTOK + (l0v) + r) * 32 + c2;          \
        size_t vb = (((size_t)((camv)*NH + hq))*HD + r) * (LTOK/2) + ((l0v) >> 1) + c2;\
        kh0 = *reinterpret_cast<const uint4*>(kph + kb);                              \
        kh1 = *reinterpret_cast<const uint4*>(kph + kb + 4);                          \
        kl0 = *reinterpret_cast<const uint4*>(kpl + kb);                              \
        kl1 = *reinterpret_cast<const uint4*>(kpl + kb + 4);                          \
        vh0 = *reinterpret_cast<const uint4*>(vph + vb);                              \
        vh1 = *reinterpret_cast<const uint4*>(vph + vb + 4);                          \
        vl0 = *reinterpret_cast<const uint4*>(vpl + vb);                              \
        vl1 = *reinterpret_cast<const uint4*>(vpl + vb + 4);                          \
    } while (0)

    LOADKV(CAM_OF(0), 0);

    for (int kv0 = 0; kv0 < Tk; kv0 += 64) {
        {
            int w = r * FA_SK + c2;
            *reinterpret_cast<uint4*>(&khw[w]) = kh0;
            *reinterpret_cast<uint4*>(&khw[w + 4]) = kh1;
            *reinterpret_cast<uint4*>(&klw[w]) = kl0;
            *reinterpret_cast<uint4*>(&klw[w + 4]) = kl1;
            *reinterpret_cast<uint4*>(&vhw[w]) = vh0;
            *reinterpret_cast<uint4*>(&vhw[w + 4]) = vh1;
            *reinterpret_cast<uint4*>(&vlw[w]) = vl0;
            *reinterpret_cast<uint4*>(&vlw[w + 4]) = vl1;
        }
        __syncthreads();

        if (kv0 + 64 < Tk) {
            int nx = kv0 + 64;
            LOADKV(CAM_OF(nx), nx & (LTOK-1));
        }

        float sacc[8][4];
        #pragma unroll
        for (int i = 0; i < 8; i++)
            #pragma unroll
            for (int t = 0; t < 4; t++) sacc[i][t] = 0.f;
        #pragma unroll
        for (int kk = 0; kk < 4; kk++) {
            #pragma unroll
            for (int ni = 0; ni < 8; ni++) {
                uint32_t bh[2], bl[2];
                int off = (ni * 8 + g) * FA_SK + kk * 8 + tg;
                bh[0] = khw[off]; bh[1] = khw[off + 4];
                bl[0] = klw[off]; bl[1] = klw[off + 4];
                mma_bf16(sacc[ni], qh[kk], bh);
                mma_bf16(sacc[ni], qh[kk], bl);
                mma_bf16(sacc[ni], ql[kk], bh);
            }
        }

        float mx0 = -1e30f, mx1 = -1e30f;
        #pragma unroll
        for (int ni = 0; ni < 8; ni++) {
            mx0 = fmaxf(mx0, fmaxf(sacc[ni][0], sacc[ni][1]));
            mx1 = fmaxf(mx1, fmaxf(sacc[ni][2], sacc[ni][3]));
        }
        mx0 = fmaxf(mx0, __shfl_xor_sync(0xffffffff, mx0, 1));
        mx0 = fmaxf(mx0, __shfl_xor_sync(0xffffffff, mx0, 2));
        mx1 = fmaxf(mx1, __shfl_xor_sync(0xffffffff, mx1, 1));
        mx1 = fmaxf(mx1, __shfl_xor_sync(0xffffffff, mx1, 2));
        float nm0 = fmaxf(m0, mx0), nm1 = fmaxf(m1, mx1);
        float al0 = __expf(m0 - nm0), al1 = __expf(m1 - nm1);
        float rs0 = 0.f, rs1 = 0.f;
        #pragma unroll
        for (int ni = 0; ni < 8; ni++) {
            sacc[ni][0] = __expf(sacc[ni][0] - nm0);
            sacc[ni][1] = __expf(sacc[ni][1] - nm0);
            sacc[ni][2] = __expf(sacc[ni][2] - nm1);
            sacc[ni][3] = __expf(sacc[ni][3] - nm1);
            rs0 += sacc[ni][0] + sacc[ni][1];
            rs1 += sacc[ni][2] + sacc[ni][3];
        }
        rs0 += __shfl_xor_sync(0xffffffff, rs0, 1);
        rs0 += __shfl_xor_sync(0xffffffff, rs0, 2);
        rs1 += __shfl_xor_sync(0xffffffff, rs1, 1);
        rs1 += __shfl_xor_sync(0xffffffff, rs1, 2);
        l0 = l0 * al0 + rs0;  l1 = l1 * al1 + rs1;
        m0 = nm0;  m1 = nm1;
        #pragma unroll
        for (int nd = 0; nd < 8; nd++) {
            oacc[nd][0] *= al0; oacc[nd][1] *= al0;
            oacc[nd][2] *= al1; oacc[nd][3] *= al1;
        }

        #pragma unroll
        for (int kk = 0; kk < 4; kk++) {
            uint32_t ph[4], pl[4];
            cvt_hl(sacc[2*kk][0],   sacc[2*kk][1],   ph[0], pl[0]);
            cvt_hl(sacc[2*kk][2],   sacc[2*kk][3],   ph[1], pl[1]);
            cvt_hl(sacc[2*kk+1][0], sacc[2*kk+1][1], ph[2], pl[2]);
            cvt_hl(sacc[2*kk+1][2], sacc[2*kk+1][3], ph[3], pl[3]);
            #pragma unroll
            for (int nd = 0; nd < 8; nd++) {
                uint32_t vh[2], vl[2];
                int off = (nd * 8 + g) * FA_SK + kk * 8 + tg;
                vh[0] = vhw[off]; vh[1] = vhw[off + 4];
                vl[0] = vlw[off]; vl[1] = vlw[off + 4];
                mma_bf16(oacc[nd], ph, vh);
                mma_bf16(oacc[nd], ph, vl);
                mma_bf16(oacc[nd], pl, vh);
            }
        }
        __syncthreads();
    }
    #undef LOADKV
    #undef CAM_OF

    float il0 = 1.0f / l0, il1 = 1.0f / l1;
    float* Ob = Og + ((size_t)nh * LTOK + q0) * HD;
    #pragma unroll
    for (int nd = 0; nd < 8; nd++) {
        int col = nd * 8 + tg * 2;
        *reinterpret_cast<float2*>(&Ob[(size_t)row0 * HD + col]) =
            make_float2(oacc[nd][0] * il0, oacc[nd][1] * il0);
        *reinterpret_cast<float2*>(&Ob[(size_t)(row0 + 8) * HD + col]) =
            make_float2(oacc[nd][2] * il1, oacc[nd][3] * il1);
    }
}

// ---------------- output apply ----------------
__global__ void k_apply_out(const float* __restrict__ O, const float* __restrict__ Mi,
                            uint32_t* __restrict__ omh, uint32_t* __restrict__ oml) {
    int idx = blockIdx.x * blockDim.x + threadIdx.x;
    if (idx >= NAPP) return;
    int g = idx & 15, h = (idx >> 4) & 3, t = (idx >> 6) & (LTOK-1), n = idx >> 16;
    const float* M = Mi + ((size_t)(n*LTOK + t))*16;
    const float* s = O + (((size_t)(n*NH + h))*LTOK + t)*HD + g*4;
    float x0=s[0], x1=s[1], x2=s[2], x3=s[3];
    float d[4];
    #pragma unroll
    for (int i = 0; i < 4; i++)
        d[i] = M[i*4+0]*x0 + M[i*4+1]*x1 + M[i*4+2]*x2 + M[i*4+3]*x3;
    size_t w = (((size_t)(n*LTOK + t))*CC + h*HD + g*4) >> 1;
    uint32_t h0, l0, h1, l1;
    cvt_hl(d[0], d[1], h0, l0);
    cvt_hl(d[2], d[3], h1, l1);
    omh[w] = h0;   oml[w] = l0;
    omh[w+1] = h1; oml[w+1] = l1;
}

// ---------------- layout kernels ----------------
__global__ void k_build_x(const float* __restrict__ f, float* __restrict__ x,
                          uint32_t* __restrict__ xh, uint32_t* __restrict__ xl,
                          uint32_t* __restrict__ xph, uint32_t* __restrict__ xpl) {
    int idx = blockIdx.x * blockDim.x + threadIdx.x;
    if (idx >= XW) return;
    int c2 = idx & 127;
    int l  = (idx >> 7) & (LTOK-1);
    int n  = idx >> 17;
    int c  = c2 * 2;
    float a = f[((size_t)n*CC + c)*LTOK + l];
    float b = f[((size_t)n*CC + c + 1)*LTOK + l];
    reinterpret_cast<float2*>(x)[idx] = make_float2(a, b);
    uint32_t h, lw;
    cvt_hl(a, b, h, lw);
    xh[idx] = h; xl[idx] = lw;
    xph[idx] = h; xpl[idx] = lw;
}

__global__ void k_final(const float* __restrict__ x, float* __restrict__ o) {
    int idx = blockIdx.x * blockDim.x + threadIdx.x;
    if (idx >= ROWS_*CC) return;
    int l = idx & (LTOK-1);
    int c = (idx >> 10) & (CC-1);
    int n = idx >> 18;
    o[idx] = x[((size_t)n*LTOK + l)*CC + c];
}

// ---------------- PRoPE matrix build (Mq also serves cross-KV) ---------------
__device__ __forceinline__ void prope_forward(const float* vm, const float* Kc,
                                              float u, float vyy, float* M) {
    float fx = Kc[0] * (1.0f/128.0f), fy = Kc[4] * (1.0f/128.0f);
    float cx = Kc[2] * (1.0f/128.0f), cy = Kc[5] * (1.0f/128.0f);
    float a = cx - u, b = cy - vyy;
    #pragma unroll
    for (int c = 0; c < 4; c++) {
        M[0*4+c] = fx*vm[0*4+c] + a*vm[2*4+c];
        M[1*4+c] = fy*vm[1*4+c] + b*vm[2*4+c];
        M[2*4+c] = vm[2*4+c];
        M[3*4+c] = vm[3*4+c];
    }
}

__global__ void k_prope_q(const float* __restrict__ vms, const float* __restrict__ Ks,
                          float* __restrict__ Mq, float* __restrict__ Mqi) {
    int idx = blockIdx.x * blockDim.x + threadIdx.x;
    if (idx >= NVB*LTOK) return;
    int n = idx >> 10, t = idx & (LTOK-1);
    int px = t & 31, py = t >> 5;
    float u  = (px + 0.5f) * (1.0f/32.0f);
    float vy = (py + 0.5f) * (1.0f/32.0f);
    const float* vm = vms + n*16;
    const float* Kc = Ks + n*9;
    float M[16];
    prope_forward(vm, Kc, u, vy, M);
    #pragma unroll
    for (int i = 0; i < 16; i++) Mq[idx*16+i] = M[i];

    float r00=vm[0],r01=vm[1],r02=vm[2],  t0=vm[3];
    float r10=vm[4],r11=vm[5],r12=vm[6],  t1=vm[7];
    float r20=vm[8],r21=vm[9],r22=vm[10], t2=vm[11];
    float det = r00*(r11*r22-r12*r21) - r01*(r10*r22-r12*r20) + r02*(r10*r21-r11*r20);
    float id = 1.0f/det;
    float Ri[9];
    Ri[0]=(r11*r22-r12*r21)*id; Ri[1]=(r02*r21-r01*r22)*id; Ri[2]=(r01*r12-r02*r11)*id;
    Ri[3]=(r12*r20-r10*r22)*id; Ri[4]=(r00*r22-r02*r20)*id; Ri[5]=(r02*r10-r00*r12)*id;
    Ri[6]=(r10*r21-r11*r20)*id; Ri[7]=(r01*r20-r00*r21)*id; Ri[8]=(r00*r11-r01*r10)*id;
    float ti0 = -(Ri[0]*t0 + Ri[1]*t1 + Ri[2]*t2);
    float ti1 = -(Ri[3]*t0 + Ri[4]*t1 + Ri[5]*t2);
    float ti2 = -(Ri[6]*t0 + Ri[7]*t1 + Ri[8]*t2);
    float fx = Kc[0]*(1.0f/128.0f), fy = Kc[4]*(1.0f/128.0f);
    float cx = Kc[2]*(1.0f/128.0f), cy = Kc[5]*(1.0f/128.0f);
    float a = cx - u, b = cy - vy;
    float ifx = 1.0f/fx, ify = 1.0f/fy;
    float Mi[16];
    float tv[3] = {ti0, ti1, ti2};
    #pragma unroll
    for (int i = 0; i < 3; i++) {
        Mi[i*4+0] = Ri[i*3+0]*ifx;
        Mi[i*4+1] = Ri[i*3+1]*ify;
        Mi[i*4+2] = -Ri[i*3+0]*a*ifx - Ri[i*3+1]*b*ify + Ri[i*3+2];
        Mi[i*4+3] = tv[i];
    }
    Mi[12]=0.f; Mi[13]=0.f; Mi[14]=0.f; Mi[15]=1.f;
    #pragma unroll
    for (int i = 0; i < 16; i++) Mqi[idx*16+i] = Mi[i];
}

// ---------------- per-token applies: Q + per-camera K/V (no gather) ----------
__global__ void k_apply_all(const float* __restrict__ qkv, int stride,
                            const float* __restrict__ Mqi, const float* __restrict__ Mq,
                            uint32_t* __restrict__ qph, uint32_t* __restrict__ qpl,
                            uint32_t* __restrict__ kph, uint32_t* __restrict__ kpl,
                            uint32_t* __restrict__ vph, uint32_t* __restrict__ vpl)
{
    int idx = blockIdx.x * blockDim.x + threadIdx.x;
    if (idx < NAPP) {
        // ---- Q: Mqi^T apply, scaled 1/8, packed ----
        int g = idx & 15, h = (idx >> 4) & 3, t = (idx >> 6) & (LTOK-1), n = idx >> 16;
        const float* M = Mqi + ((size_t)(n*LTOK + t))*16;
        const float* s = qkv + ((size_t)(n*LTOK + t))*stride + h*HD + g*4;
        float x0=s[0], x1=s[1], x2=s[2], x3=s[3];
        float d[4];
        #pragma unroll
        for (int i = 0; i < 4; i++)
            d[i] = M[0*4+i]*x0 + M[1*4+i]*x1 + M[2*4+i]*x2 + M[3*4+i]*x3;
        uint32_t h0, l0, h1, l1;
        cvt_hl(d[0]*0.125f, d[1]*0.125f, h0, l0);
        cvt_hl(d[2]*0.125f, d[3]*0.125f, h1, l1);
        size_t wb = (((size_t)(n*NH + h))*LTOK + t)*32 + g*2;
        qph[wb] = h0;   qpl[wb] = l0;
        qph[wb+1] = h1; qpl[wb+1] = l1;
    } else if (idx < 2*NAPP) {
        // ---- K per camera: Mq apply, packed ----
        int i2 = idx - NAPP;
        int g = i2 & 15, h = (i2 >> 4) & 3, t = (i2 >> 6) & (LTOK-1), n = i2 >> 16;
        const float* M = Mq + ((size_t)(n*LTOK + t))*16;
        const float* s = qkv + ((size_t)(n*LTOK + t))*stride + 256 + h*HD + g*4;
        float x0=s[0], x1=s[1], x2=s[2], x3=s[3];
        float d[4];
        #pragma unroll
        for (int i = 0; i < 4; i++)
            d[i] = M[i*4+0]*x0 + M[i*4+1]*x1 + M[i*4+2]*x2 + M[i*4+3]*x3;
        size_t wb = (((size_t)(n*NH + h))*LTOK + t)*32 + g*2;
        uint32_t h0, l0, h1, l1;
        cvt_hl(d[0], d[1], h0, l0);
        cvt_hl(d[2], d[3], h1, l1);
        kph[wb] = h0;   kpl[wb] = l0;
        kph[wb+1] = h1; kpl[wb+1] = l1;
    } else if (idx < 3*NAPP) {
        // ---- V per camera (transposed, pair-packed) ----
        int i2 = idx - 2*NAPP;
        int tt = i2 & (LTOK-1);
        int rest = i2 >> 10;
        int g = rest & 15, h = (rest >> 4) & 3, n = rest >> 6;
        const float* M = Mq + ((size_t)(n*LTOK + tt))*16;
        const float* s = qkv + ((size_t)(n*LTOK + tt))*stride + 512 + h*HD + g*4;
        float x0=s[0], x1=s[1], x2=s[2], x3=s[3];
        #pragma unroll
        for (int i = 0; i < 4; i++) {
            float v = M[i*4+0]*x0 + M[i*4+1]*x1 + M[i*4+2]*x2 + M[i*4+3]*x3;
            float vn = __shfl_down_sync(0xffffffff, v, 1);
            if ((tt & 1) == 0) {
                uint32_t hh2, ll2;
                cvt_hl(v, vn, hh2, ll2);
                size_t wb = ((size_t)(n*NH + h)*HD + g*4 + i)*(LTOK >> 1) + (tt >> 1);
                vph[wb] = hh2; vpl[wb] = ll2;
            }
        }
    }
}

// ---------------- layernorm: sums nparts partials, optional bf16 + cat writes --
__global__ void k_ln(float* __restrict__ dst, const float* __restrict__ parts, int nparts,
                     const float* __restrict__ w, const float* __restrict__ b, int add,
                     uint32_t* __restrict__ oh, uint32_t* __restrict__ ol,
                     uint32_t* __restrict__ oh2, uint32_t* __restrict__ ol2,
                     uint32_t* __restrict__ ch, uint32_t* __restrict__ cl, int catHalf) {
    __shared__ float red[256];
    int row = blockIdx.x, tid = threadIdx.x;
    float v = parts[(size_t)row*CC + tid];
    for (int p = 1; p < nparts; p++)
        v += parts[(size_t)p*ROWS_*CC + (size_t)row*CC + tid];
    red[tid] = v; __syncthreads();
    for (int s = 128; s > 0; s >>= 1) { if (tid < s) red[tid] += red[tid+s]; __syncthreads(); }
    float mu = red[0] * (1.0f/CC); __syncthreads();
    float d = v - mu;
    red[tid] = d * d; __syncthreads();
    for (int s = 128; s > 0; s >>= 1) { if (tid < s) red[tid] += red[tid+s]; __syncthreads(); }
    float var = red[0] * (1.0f/CC);
    float o = d * rsqrtf(var + 1e-5f) * w[tid] + b[tid];
    float fin;
    if (add) { fin = dst[(size_t)row*CC + tid] + o; dst[(size_t)row*CC + tid] = fin; }
    else     { fin = o; dst[(size_t)row*CC + tid] = fin; }
    if (oh || ch) {
        __syncthreads();
        red[tid] = fin;
        __syncthreads();
        if (tid < 128) {
            uint32_t h, l;
            cvt_hl(red[2*tid], red[2*tid+1], h, l);
            if (oh) {
                oh[(size_t)row*(CC/2) + tid] = h;
                ol[(size_t)row*(CC/2) + tid] = l;
                if (oh2) {
                    oh2[(size_t)row*(CC/2) + tid] = h;
                    ol2[(size_t)row*(CC/2) + tid] = l;
                }
            }
            if (ch) {
                size_t cw = (size_t)row*(FFNI/2) + catHalf*128 + tid;
                ch[cw] = h; cl[cw] = l;
            }
        }
    }
}

// ---------------- host driver ----------------
static const int GSMEM128 = 98304;
static const int GSMEM64  = 73728;

static void gemm128(const uint32_t* Ah, const uint32_t* Al,
                    const uint32_t* A2h, const uint32_t* A2l, int nsplit,
                    const uint32_t* Bh, const uint32_t* Bl,
                    float* C, int M, int N, int K) {
    dim3 g(N/128, M/128, 1);
    tc_gemm<128,0><<<g, 256, GSMEM128>>>(Ah, Al, A2h, A2l, nsplit, Bh, Bl,
                                         C, nullptr, nullptr, M, N, K, K);
}
static void gemm64s(const uint32_t* Ah, const uint32_t* Al,
                    const uint32_t* Bh, const uint32_t* Bl,
                    float* C, int M, int N, int Ktot, int nz) {
    dim3 g(N/64, M/128, nz);
    tc_gemm<64,0><<<g, 256, GSMEM64>>>(Ah, Al, Ah, Al, 1<<30, Bh, Bl,
                                       C, nullptr, nullptr, M, N, Ktot/nz, Ktot);
}
static void gemm_gelu_hl(const uint32_t* Ah, const uint32_t* Al,
                         const uint32_t* Bh, const uint32_t* Bl,
                         uint32_t* Oh, uint32_t* Ol, int M, int N, int K) {
    dim3 g(N/128, M/128, 1);
    tc_gemm<128,1><<<g, 256, GSMEM128>>>(Ah, Al, Ah, Al, 1<<30, Bh, Bl,
                                         nullptr, Oh, Ol, M, N, K, K);
}

extern "C" void kernel_launch(void* const* d_in, const int* in_sizes, int n_in,
                              void* d_out, int out_size) {
    const float* feats = (const float*)d_in[0];
    const float* vms   = (const float*)d_in[1];
    const float* Ks    = (const float*)d_in[2];
    const float* Wq    = (const float*)d_in[3];
    const float* Wk    = (const float*)d_in[4];
    const float* Wv    = (const float*)d_in[5];
    const float* Wm    = (const float*)d_in[6];
    const float* n1w   = (const float*)d_in[7];
    const float* n1b   = (const float*)d_in[8];
    const float* W1    = (const float*)d_in[9];
    const float* W2    = (const float*)d_in[10];
    const float* n2w   = (const float*)d_in[11];
    const float* n2b   = (const float*)d_in[12];

    cudaFuncSetAttribute(tc_gemm<128,0>, cudaFuncAttributeMaxDynamicSharedMemorySize, GSMEM128);
    cudaFuncSetAttribute(tc_gemm<128,1>, cudaFuncAttributeMaxDynamicSharedMemorySize, GSMEM128);
    cudaFuncSetAttribute(tc_gemm<64,0>,  cudaFuncAttributeMaxDynamicSharedMemorySize, GSMEM64);

    void* p;
    float *x,*qkv,*O,*msg,*msg2,*h22,*Mq,*Mqi;
    uint32_t *qph,*qpl,*kph,*kpl,*vph,*vpl;
    uint32_t *xh,*xl,*xpreh,*xprel,*omh,*oml,*cath,*catl,*hh,*hl,*wh,*wl;
    cudaGetSymbolAddress(&p, g_x);    x   = (float*)p;
    cudaGetSymbolAddress(&p, g_qkv);  qkv = (float*)p;
    cudaGetSymbolAddress(&p, g_qph);  qph = (uint32_t*)p;
    cudaGetSymbolAddress(&p, g_qpl);  qpl = (uint32_t*)p;
    cudaGetSymbolAddress(&p, g_kph);  kph = (uint32_t*)p;
    cudaGetSymbolAddress(&p, g_kpl);  kpl = (uint32_t*)p;
    cudaGetSymbolAddress(&p, g_vph);  vph = (uint32_t*)p;
    cudaGetSymbolAddress(&p, g_vpl);  vpl = (uint32_t*)p;
    cudaGetSymbolAddress(&p, g_O);    O   = (float*)p;
    cudaGetSymbolAddress(&p, g_msg);  msg = (float*)p;
    cudaGetSymbolAddress(&p, g_msg2); msg2= (float*)p;
    cudaGetSymbolAddress(&p, g_h22);  h22 = (float*)p;
    cudaGetSymbolAddress(&p, g_Mq);   Mq  = (float*)p;
    cudaGetSymbolAddress(&p, g_Mqi);  Mqi = (float*)p;
    cudaGetSymbolAddress(&p, g_xh);    xh    = (uint32_t*)p;
    cudaGetSymbolAddress(&p, g_xl);    xl    = (uint32_t*)p;
    cudaGetSymbolAddress(&p, g_xpreh); xpreh = (uint32_t*)p;
    cudaGetSymbolAddress(&p, g_xprel); xprel = (uint32_t*)p;
    cudaGetSymbolAddress(&p, g_omh);   omh   = (uint32_t*)p;
    cudaGetSymbolAddress(&p, g_oml);   oml   = (uint32_t*)p;
    cudaGetSymbolAddress(&p, g_cath);  cath  = (uint32_t*)p;
    cudaGetSymbolAddress(&p, g_catl);  catl  = (uint32_t*)p;
    cudaGetSymbolAddress(&p, g_hh);    hh    = (uint32_t*)p;
    cudaGetSymbolAddress(&p, g_hl);    hl    = (uint32_t*)p;
    cudaGetSymbolAddress(&p, g_wh);    wh    = (uint32_t*)p;
    cudaGetSymbolAddress(&p, g_wl);    wl    = (uint32_t*)p;

    const int ROWS = ROWS_;
    const int NEL  = ROWS * CC;

    k_cvt_all<<<WTOT/256, 256>>>(Wq, Wk, Wv, Wm, W1, W2, wh, wl);
    k_build_x<<<(XW+255)/256, 256>>>(feats, x, xh, xl, xpreh, xprel);
    k_prope_q<<<(NVB*LTOK+255)/256, 256>>>(vms, Ks, Mq, Mqi);

    for (int ly = 0; ly < 2; ly++) {
        // ---------- self attention ----------
        gemm128(xh, xl, xh, xl, 1<<30,
                wh + WQKV0 + (ly*2+0)*98304, wl + WQKV0 + (ly*2+0)*98304,
                qkv, ROWS, 768, CC);
        k_apply_all<<<(3*NAPP)/256, 256>>>(qkv, 768, Mqi, Mq,
                                           qph, qpl, kph, kpl, vph, vpl);
        k_flash<<<dim3(LTOK/128, NVB*NH), 256>>>(qph, qpl, kph, kpl, vph, vpl, O, LTOK);
        k_apply_out<<<NAPP/256, 256>>>(O, Mqi, omh, oml);
        gemm64s(omh, oml, wh + WMO + (ly*2+0)*32768, wl + WMO + (ly*2+0)*32768,
                msg2, ROWS, CC, CC, 2);
        k_ln<<<ROWS, 256>>>(x, msg2, 2, n1w + (ly*2+0)*CC, n1b + (ly*2+0)*CC, 1,
                            xh, xl, nullptr, nullptr, cath, catl, 0);

        // ---------- cross attention (per-camera K/V, dedup) ----------
        gemm128(xh, xl, xpreh, xprel, 256,
                wh + WQKV0 + (ly*2+1)*98304, wl + WQKV0 + (ly*2+1)*98304,
                qkv, ROWS, 768, CC);
        k_apply_all<<<(3*NAPP)/256, 256>>>(qkv, 768, Mqi, Mq,
                                           qph, qpl, kph, kpl, vph, vpl);
        k_flash<<<dim3(LTOK/128, NVB*NH), 256>>>(qph, qpl, kph, kpl, vph, vpl, O, TKX);
        k_apply_out<<<NAPP/256, 256>>>(O, Mqi, omh, oml);
        gemm64s(omh, oml, wh + WMO + (ly*2+1)*32768, wl + WMO + (ly*2+1)*32768,
                msg2, ROWS, CC, CC, 2);
        k_ln<<<ROWS, 256>>>(msg, msg2, 2, n1w + (ly*2+1)*CC, n1b + (ly*2+1)*CC, 0,
                            nullptr, nullptr, nullptr, nullptr, cath, catl, 1);

        // ---------- FFN ----------
        gemm_gelu_hl(cath, catl,
                     wh + W1O + (size_t)ly*524288, wl + W1O + (size_t)ly*524288,
                     hh, hl, ROWS, FFNH, FFNI);
        gemm64s(hh, hl, wh + W2O + (size_t)ly*262144, wl + W2O + (size_t)ly*262144,
                h22, ROWS, CC, FFNH, 4);
        k_ln<<<ROWS, 256>>>(x, h22, 4, n2w + ly*CC, n2b + ly*CC, 1,
                            xh, xl, xpreh, xprel, nullptr, nullptr, 0);
    }

    k_final<<<(NEL+255)/256, 256>>>(x, (float*)d_out);
}

// round 17
// speedup vs baseline: 1.1004x; 1.0669x over previous
#include <cuda_runtime.h>
#include <cuda_bf16.h>
#include <math.h>
#include <stdint.h>

// ---------------- problem constants ----------------
#define NVB   6
#define VV    3
#define BB    2
#define CC    256
#define LTOK  1024
#define TKX   2048
#define NH    4
#define HD    64
#define FFNI  512
#define FFNH  2048

#define ROWS_ (NVB*LTOK)          // 6144
#define XW    (NVB*LTOK*CC/2)
#define NAPP  (NVB*LTOK*NH*16)    // 393216

// ---------------- device scratch ----------------
__device__ float g_x   [ROWS_*CC];
__device__ float g_qkv [ROWS_*768];
__device__ uint32_t g_qph[NVB*NH*LTOK*32], g_qpl[NVB*NH*LTOK*32];
__device__ uint32_t g_kph[NVB*NH*LTOK*32], g_kpl[NVB*NH*LTOK*32];   // per-CAM K
__device__ uint32_t g_vph[NVB*NH*LTOK*32], g_vpl[NVB*NH*LTOK*32];   // per-CAM V^T
__device__ float g_O   [NVB*NH*LTOK*HD];
__device__ float g_msg [ROWS_*CC];
__device__ float g_msg2[2*ROWS_*CC];
__device__ float g_h22 [4*ROWS_*CC];
__device__ float g_Mq  [NVB*LTOK*16];
__device__ float g_Mqi [NVB*LTOK*16];

__device__ uint32_t g_xh   [XW],  g_xl   [XW];
__device__ uint32_t g_xpreh[XW],  g_xprel[XW];
__device__ uint32_t g_omh  [XW],  g_oml  [XW];
__device__ uint32_t g_cath [ROWS_*FFNI/2], g_catl[ROWS_*FFNI/2];
__device__ uint32_t g_hh   [ROWS_*FFNH/2], g_hl  [ROWS_*FFNH/2];
#define WQKV0 0
#define WMO   393216
#define W1O   524288
#define W2O   1572864
#define WTOT  2097152
__device__ uint32_t g_wh[WTOT], g_wl[WTOT];

// ---------------- helpers ----------------
__device__ __forceinline__ void cvt_hl(float x, float y, uint32_t& hi, uint32_t& lo) {
    __nv_bfloat162 h = __floats2bfloat162_rn(x, y);
    float rx = x - __bfloat162float(h.x);
    float ry = y - __bfloat162float(h.y);
    __nv_bfloat162 l = __floats2bfloat162_rn(rx, ry);
    hi = *reinterpret_cast<uint32_t*>(&h);
    lo = *reinterpret_cast<uint32_t*>(&l);
}

__device__ __forceinline__ void mma_bf16(float* c, const uint32_t* a, const uint32_t* b) {
    asm volatile(
        "mma.sync.aligned.m16n8k16.row.col.f32.bf16.bf16.f32 "
        "{%0,%1,%2,%3}, {%4,%5,%6,%7}, {%8,%9}, {%0,%1,%2,%3};"
        : "+f"(c[0]), "+f"(c[1]), "+f"(c[2]), "+f"(c[3])
        : "r"(a[0]), "r"(a[1]), "r"(a[2]), "r"(a[3]), "r"(b[0]), "r"(b[1]));
}

__device__ __forceinline__ void ldsm4(uint32_t* r, uint32_t addr) {
    asm volatile("ldmatrix.sync.aligned.m8n8.x4.shared.b16 {%0,%1,%2,%3}, [%4];"
        : "=r"(r[0]), "=r"(r[1]), "=r"(r[2]), "=r"(r[3]) : "r"(addr));
}

__device__ __forceinline__ uint32_t smem_u32(const void* p) {
    uint32_t a;
    asm("{ .reg .u64 t; cvta.to.shared.u64 t, %1; cvt.u32.u64 %0, t; }" : "=r"(a) : "l"(p));
    return a;
}

__device__ __forceinline__ void cp16(uint32_t smem, const void* g) {
    asm volatile("cp.async.cg.shared.global [%0], [%1], 16;" :: "r"(smem), "l"(g));
}
#define CP_COMMIT() asm volatile("cp.async.commit_group;")
#define CP_WAIT(N)  asm volatile("cp.async.wait_group %0;" :: "n"(N))

// ---------------- all-weight conversion + QKV repack ----------------
__global__ void k_cvt_all(const float* __restrict__ Wq, const float* __restrict__ Wk,
                          const float* __restrict__ Wv, const float* __restrict__ Wm,
                          const float* __restrict__ W1, const float* __restrict__ W2,
                          uint32_t* __restrict__ wh, uint32_t* __restrict__ wl) {
    int i = blockIdx.x * blockDim.x + threadIdx.x;
    if (i >= WTOT) return;
    const float* src;
    if (i < WMO) {
        int lyp  = i / 98304;
        int sub  = i % 98304;
        int which = sub / 32768;
        int woff  = sub % 32768;
        const float* base = (which == 0) ? Wq : (which == 1) ? Wk : Wv;
        src = base + (size_t)lyp * 65536 + (size_t)woff * 2;
    } else if (i < W1O) {
        src = Wm + (size_t)(i - WMO) * 2;
    } else if (i < W2O) {
        src = W1 + (size_t)(i - W1O) * 2;
    } else {
        src = W2 + (size_t)(i - W2O) * 2;
    }
    float2 v = *reinterpret_cast<const float2*>(src);
    uint32_t h, l;
    cvt_hl(v.x, v.y, h, l);
    wh[i] = h; wl[i] = l;
}

// ---------------- tensor-core bf16x3 GEMM (BN template, split-K via z) -------
// __launch_bounds__(256, 2): force <=128 regs so 2 CTAs/SM co-reside (the
// R16 ncu capture showed 129 regs -> reg-file cap at 1 CTA/SM, tensor=34%).
template<int BN, int OUT>
__global__ __launch_bounds__(256, 2)
void tc_gemm(const uint32_t* __restrict__ Ah, const uint32_t* __restrict__ Al,
             const uint32_t* __restrict__ A2h, const uint32_t* __restrict__ A2l,
             int nsplit,
             const uint32_t* __restrict__ Bh, const uint32_t* __restrict__ Bl,
             float* __restrict__ C, uint32_t* __restrict__ Oh, uint32_t* __restrict__ Ol,
             int M, int N, int K, int Krow)
{
    constexpr int WARPS_N = BN / 32;
    constexpr int WMX = 128 / (8 / WARPS_N);
    constexpr int MT = WMX / 16;
    constexpr int B_HI = BN * 48;
    constexpr int STAGE = 12288 + 2 * B_HI;

    extern __shared__ uint32_t smem[];
    const uint32_t sb0 = smem_u32(smem);

    const int m0 = blockIdx.y * 128;
    const int n0 = blockIdx.x * BN;
    const int kz = blockIdx.z;
    const int tid = threadIdx.x;
    const int wid = tid >> 5, lane = tid & 31;
    const int g = lane >> 2, tg = lane & 3;
    const int warp_m = wid / WARPS_N, warp_n = wid % WARPS_N;
    const int wm0 = warp_m * WMX, wn0 = warp_n * 32;
    const int Krow2 = Krow >> 1;
    const size_t kzoff = (size_t)kz * (K >> 1);

    const int rowa = tid >> 1, hw = (tid & 1) * 4;

    const int a_lrow = lane & 15;
    const int a_lcol = (lane >> 4) * 4;
    const int b_lrow = (lane & 7) + ((lane >> 4) << 3);
    const int b_lcol = ((lane >> 3) & 1) * 4;

    float acc[MT][4][4];
    #pragma unroll
    for (int i = 0; i < MT; i++)
        #pragma unroll
        for (int j = 0; j < 4; j++)
            #pragma unroll
            for (int r = 0; r < 4; r++) acc[i][j][r] = 0.f;

    const bool useA2 = (n0 >= nsplit);
    const uint32_t* Ab  = (useA2 ? A2h : Ah) + (size_t)(m0 + rowa) * Krow2 + hw + kzoff;
    const uint32_t* Alb = (useA2 ? A2l : Al) + (size_t)(m0 + rowa) * Krow2 + hw + kzoff;
    const uint32_t* Bb  = Bh + (size_t)(n0 + rowa) * Krow2 + hw + kzoff;
    const uint32_t* Blb = Bl + (size_t)(n0 + rowa) * Krow2 + hw + kzoff;
    C += (size_t)kz * M * N;

    const uint32_t dst_off = (uint32_t)(rowa * 12 + hw) * 4;
    const int nk = K >> 4;

    #define ISSUE(tile, stage) do {                                   \
        uint32_t sb = sb0 + (stage) * (uint32_t)STAGE;                \
        int ko = (tile) * 8;                                          \
        cp16(sb + dst_off,        Ab + ko);                           \
        cp16(sb + 6144 + dst_off, Alb + ko);                          \
        if (BN == 128 || tid < 128) {                                 \
            cp16(sb + 12288 + dst_off,        Bb + ko);               \
            cp16(sb + 12288 + B_HI + dst_off, Blb + ko);              \
        }                                                             \
    } while (0)

    #pragma unroll
    for (int s = 0; s < 3; s++) {
        if (s < nk) ISSUE(s, s);
        CP_COMMIT();
    }

    for (int kt = 0; kt < nk; kt++) {
        if (kt + 3 < nk) ISSUE(kt + 3, (kt + 3) & 3);
        CP_COMMIT();
        CP_WAIT(3);
        __syncthreads();

        const uint32_t sb = sb0 + (kt & 3) * (uint32_t)STAGE;
        uint32_t ah[MT][4], al[MT][4], bh2[4][2], bl2[4][2];
        #pragma unroll
        for (int mi = 0; mi < MT; mi++) {
            uint32_t woff = (uint32_t)((wm0 + mi*16 + a_lrow) * 12 + a_lcol) * 4;
            ldsm4(ah[mi], sb + woff);
            ldsm4(al[mi], sb + 6144 + woff);
        }
        #pragma unroll
        for (int p = 0; p < 2; p++) {
            uint32_t woff = (uint32_t)((wn0 + p*16 + b_lrow) * 12 + b_lcol) * 4;
            uint32_t r[4];
            ldsm4(r, sb + 12288 + woff);
            bh2[2*p][0] = r[0]; bh2[2*p][1] = r[1];
            bh2[2*p+1][0] = r[2]; bh2[2*p+1][1] = r[3];
            ldsm4(r, sb + 12288 + B_HI + woff);
            bl2[2*p][0] = r[0]; bl2[2*p][1] = r[1];
            bl2[2*p+1][0] = r[2]; bl2[2*p+1][1] = r[3];
        }
        #pragma unroll
        for (int mi = 0; mi < MT; mi++)
            #pragma unroll
            for (int ni = 0; ni < 4; ni++) {
                mma_bf16(acc[mi][ni], ah[mi], bh2[ni]);
                mma_bf16(acc[mi][ni], ah[mi], bl2[ni]);
                mma_bf16(acc[mi][ni], al[mi], bh2[ni]);
            }
        __syncthreads();
    }
    #undef ISSUE

    #pragma unroll
    for (int mi = 0; mi < MT; mi++) {
        #pragma unroll
        for (int ni = 0; ni < 4; ni++) {
            long long row0 = m0 + wm0 + mi * 16 + g;
            int col = n0 + wn0 + ni * 8 + tg * 2;
            if (OUT == 0) {
                *reinterpret_cast<float2*>(&C[row0 * N + col]) =
                    make_float2(acc[mi][ni][0], acc[mi][ni][1]);
                *reinterpret_cast<float2*>(&C[(row0 + 8) * N + col]) =
                    make_float2(acc[mi][ni][2], acc[mi][ni][3]);
            } else {
                float r[4];
                #pragma unroll
                for (int t = 0; t < 4; t++) {
                    float v = acc[mi][ni][t];
                    r[t] = 0.5f * v * (1.0f + erff(v * 0.70710678118654752f));
                }
                uint32_t h0, l0, h1, l1;
                cvt_hl(r[0], r[1], h0, l0);
                cvt_hl(r[2], r[3], h1, l1);
                size_t w0 = (size_t)(row0 * N + col) >> 1;
                size_t w1 = (size_t)((row0 + 8) * N + col) >> 1;
                Oh[w0] = h0; Ol[w0] = l0;
                Oh[w1] = h1; Ol[w1] = l1;
            }
        }
    }
}

// ---------------- fused flash attention (per-camera K/V, fp32 O out) ---------
#define FA_SK 36
__global__ __launch_bounds__(256)
void k_flash(const uint32_t* __restrict__ qph, const uint32_t* __restrict__ qpl,
             const uint32_t* __restrict__ kph, const uint32_t* __restrict__ kpl,
             const uint32_t* __restrict__ vph, const uint32_t* __restrict__ vpl,
             float* __restrict__ Og, int Tk)
{
    __shared__ uint32_t khw[64*FA_SK], klw[64*FA_SK];
    __shared__ uint32_t vhw[64*FA_SK], vlw[64*FA_SK];

    const int nh = blockIdx.y;
    const int q0 = blockIdx.x * 128;
    const int tid = threadIdx.x, wid = tid >> 5, lane = tid & 31;
    const int g = lane >> 2, tg = lane & 3;

    const int nq = nh / NH, hq = nh % NH;
    const int vq = nq >> 1, bq = nq & 1;

    const uint32_t* Qh = qph + ((size_t)nh * LTOK + q0) * 32;
    const uint32_t* Ql = qpl + ((size_t)nh * LTOK + q0) * 32;

    const int row0 = wid * 16 + g;
    uint32_t qh[4][4], ql[4][4];
    #pragma unroll
    for (int kk = 0; kk < 4; kk++) {
        int w0 = row0 * 32 + kk * 8 + tg;
        int w1 = (row0 + 8) * 32 + kk * 8 + tg;
        qh[kk][0] = Qh[w0];     ql[kk][0] = Ql[w0];
        qh[kk][1] = Qh[w1];     ql[kk][1] = Ql[w1];
        qh[kk][2] = Qh[w0 + 4]; ql[kk][2] = Ql[w0 + 4];
        qh[kk][3] = Qh[w1 + 4]; ql[kk][3] = Ql[w1 + 4];
    }

    float m0 = -1e30f, m1 = -1e30f, l0 = 0.f, l1 = 0.f;
    float oacc[8][4];
    #pragma unroll
    for (int i = 0; i < 8; i++)
        #pragma unroll
        for (int t = 0; t < 4; t++) oacc[i][t] = 0.f;

    const int r = tid >> 2, c2 = (tid & 3) * 8;
    uint4 kh0, kh1, kl0, kl1, vh0, vh1, vl0, vl1;

    #define CAM_OF(kv) ((Tk == LTOK) ? nq : \
        ((((kv) >> 10) + (((kv) >> 10) >= vq ? 1 : 0)) * BB + bq))
    #define LOADKV(camv, l0v) do {                                                    \
        size_t kb = (((size_t)((camv)*NH + hq))*LTOK + (l0v) + r) * 32 + c2;          \
        size_t vb = (((size_t)((camv)*NH + hq))*HD + r) * (LTOK/2) + ((l0v) >> 1) + c2;\
        kh0 = *reinterpret_cast<const uint4*>(kph + kb);                              \
        kh1 = *reinterpret_cast<const uint4*>(kph + kb + 4);                          \
        kl0 = *reinterpret_cast<const uint4*>(kpl + kb);                              \
        kl1 = *reinterpret_cast<const uint4*>(kpl + kb + 4);                          \
        vh0 = *reinterpret_cast<const uint4*>(vph + vb);                              \
        vh1 = *reinterpret_cast<const uint4*>(vph + vb + 4);                          \
        vl0 = *reinterpret_cast<const uint4*>(vpl + vb);                              \
        vl1 = *reinterpret_cast<const uint4*>(vpl + vb + 4);                          \
    } while (0)

    LOADKV(CAM_OF(0), 0);

    for (int kv0 = 0; kv0 < Tk; kv0 += 64) {
        {
            int w = r * FA_SK + c2;
            *reinterpret_cast<uint4*>(&khw[w]) = kh0;
            *reinterpret_cast<uint4*>(&khw[w + 4]) = kh1;
            *reinterpret_cast<uint4*>(&klw[w]) = kl0;
            *reinterpret_cast<uint4*>(&klw[w + 4]) = kl1;
            *reinterpret_cast<uint4*>(&vhw[w]) = vh0;
            *reinterpret_cast<uint4*>(&vhw[w + 4]) = vh1;
            *reinterpret_cast<uint4*>(&vlw[w]) = vl0;
            *reinterpret_cast<uint4*>(&vlw[w + 4]) = vl1;
        }
        __syncthreads();

        if (kv0 + 64 < Tk) {
            int nx = kv0 + 64;
            LOADKV(CAM_OF(nx), nx & (LTOK-1));
        }

        float sacc[8][4];
        #pragma unroll
        for (int i = 0; i < 8; i++)
            #pragma unroll
            for (int t = 0; t < 4; t++) sacc[i][t] = 0.f;
        #pragma unroll
        for (int kk = 0; kk < 4; kk++) {
            #pragma unroll
            for (int ni = 0; ni < 8; ni++) {
                uint32_t bh[2], bl[2];
                int off = (ni * 8 + g) * FA_SK + kk * 8 + tg;
                bh[0] = khw[off]; bh[1] = khw[off + 4];
                bl[0] = klw[off]; bl[1] = klw[off + 4];
                mma_bf16(sacc[ni], qh[kk], bh);
                mma_bf16(sacc[ni], qh[kk], bl);
                mma_bf16(sacc[ni], ql[kk], bh);
            }
        }

        float mx0 = -1e30f, mx1 = -1e30f;
        #pragma unroll
        for (int ni = 0; ni < 8; ni++) {
            mx0 = fmaxf(mx0, fmaxf(sacc[ni][0], sacc[ni][1]));
            mx1 = fmaxf(mx1, fmaxf(sacc[ni][2], sacc[ni][3]));
        }
        mx0 = fmaxf(mx0, __shfl_xor_sync(0xffffffff, mx0, 1));
        mx0 = fmaxf(mx0, __shfl_xor_sync(0xffffffff, mx0, 2));
        mx1 = fmaxf(mx1, __shfl_xor_sync(0xffffffff, mx1, 1));
        mx1 = fmaxf(mx1, __shfl_xor_sync(0xffffffff, mx1, 2));
        float nm0 = fmaxf(m0, mx0), nm1 = fmaxf(m1, mx1);
        float al0 = __expf(m0 - nm0), al1 = __expf(m1 - nm1);
        float rs0 = 0.f, rs1 = 0.f;
        #pragma unroll
        for (int ni = 0; ni < 8; ni++) {
            sacc[ni][0] = __expf(sacc[ni][0] - nm0);
            sacc[ni][1] = __expf(sacc[ni][1] - nm0);
            sacc[ni][2] = __expf(sacc[ni][2] - nm1);
            sacc[ni][3] = __expf(sacc[ni][3] - nm1);
            rs0 += sacc[ni][0] + sacc[ni][1];
            rs1 += sacc[ni][2] + sacc[ni][3];
        }
        rs0 += __shfl_xor_sync(0xffffffff, rs0, 1);
        rs0 += __shfl_xor_sync(0xffffffff, rs0, 2);
        rs1 += __shfl_xor_sync(0xffffffff, rs1, 1);
        rs1 += __shfl_xor_sync(0xffffffff, rs1, 2);
        l0 = l0 * al0 + rs0;  l1 = l1 * al1 + rs1;
        m0 = nm0;  m1 = nm1;
        #pragma unroll
        for (int nd = 0; nd < 8; nd++) {
            oacc[nd][0] *= al0; oacc[nd][1] *= al0;
            oacc[nd][2] *= al1; oacc[nd][3] *= al1;
        }

        #pragma unroll
        for (int kk = 0; kk < 4; kk++) {
            uint32_t ph[4], pl[4];
            cvt_hl(sacc[2*kk][0],   sacc[2*kk][1],   ph[0], pl[0]);
            cvt_hl(sacc[2*kk][2],   sacc[2*kk][3],   ph[1], pl[1]);
            cvt_hl(sacc[2*kk+1][0], sacc[2*kk+1][1], ph[2], pl[2]);
            cvt_hl(sacc[2*kk+1][2], sacc[2*kk+1][3], ph[3], pl[3]);
            #pragma unroll
            for (int nd = 0; nd < 8; nd++) {
                uint32_t vh[2], vl[2];
                int off = (nd * 8 + g) * FA_SK + kk * 8 + tg;
                vh[0] = vhw[off]; vh[1] = vhw[off + 4];
                vl[0] = vlw[off]; vl[1] = vlw[off + 4];
                mma_bf16(oacc[nd], ph, vh);
                mma_bf16(oacc[nd], ph, vl);
                mma_bf16(oacc[nd], pl, vh);
            }
        }
        __syncthreads();
    }
    #undef LOADKV
    #undef CAM_OF

    float il0 = 1.0f / l0, il1 = 1.0f / l1;
    float* Ob = Og + ((size_t)nh * LTOK + q0) * HD;
    #pragma unroll
    for (int nd = 0; nd < 8; nd++) {
        int col = nd * 8 + tg * 2;
        *reinterpret_cast<float2*>(&Ob[(size_t)row0 * HD + col]) =
            make_float2(oacc[nd][0] * il0, oacc[nd][1] * il0);
        *reinterpret_cast<float2*>(&Ob[(size_t)(row0 + 8) * HD + col]) =
            make_float2(oacc[nd][2] * il1, oacc[nd][3] * il1);
    }
}

// ---------------- output apply ----------------
__global__ void k_apply_out(const float* __restrict__ O, const float* __restrict__ Mi,
                            uint32_t* __restrict__ omh, uint32_t* __restrict__ oml) {
    int idx = blockIdx.x * blockDim.x + threadIdx.x;
    if (idx >= NAPP) return;
    int g = idx & 15, h = (idx >> 4) & 3, t = (idx >> 6) & (LTOK-1), n = idx >> 16;
    const float* M = Mi + ((size_t)(n*LTOK + t))*16;
    const float* s = O + (((size_t)(n*NH + h))*LTOK + t)*HD + g*4;
    float x0=s[0], x1=s[1], x2=s[2], x3=s[3];
    float d[4];
    #pragma unroll
    for (int i = 0; i < 4; i++)
        d[i] = M[i*4+0]*x0 + M[i*4+1]*x1 + M[i*4+2]*x2 + M[i*4+3]*x3;
    size_t w = (((size_t)(n*LTOK + t))*CC + h*HD + g*4) >> 1;
    uint32_t h0, l0, h1, l1;
    cvt_hl(d[0], d[1], h0, l0);
    cvt_hl(d[2], d[3], h1, l1);
    omh[w] = h0;   oml[w] = l0;
    omh[w+1] = h1; oml[w+1] = l1;
}

// ---------------- layout kernels ----------------
__global__ void k_build_x(const float* __restrict__ f, float* __restrict__ x,
                          uint32_t* __restrict__ xh, uint32_t* __restrict__ xl,
                          uint32_t* __restrict__ xph, uint32_t* __restrict__ xpl) {
    int idx = blockIdx.x * blockDim.x + threadIdx.x;
    if (idx >= XW) return;
    int c2 = idx & 127;
    int l  = (idx >> 7) & (LTOK-1);
    int n  = idx >> 17;
    int c  = c2 * 2;
    float a = f[((size_t)n*CC + c)*LTOK + l];
    float b = f[((size_t)n*CC + c + 1)*LTOK + l];
    reinterpret_cast<float2*>(x)[idx] = make_float2(a, b);
    uint32_t h, lw;
    cvt_hl(a, b, h, lw);
    xh[idx] = h; xl[idx] = lw;
    xph[idx] = h; xpl[idx] = lw;
}

__global__ void k_final(const float* __restrict__ x, float* __restrict__ o) {
    int idx = blockIdx.x * blockDim.x + threadIdx.x;
    if (idx >= ROWS_*CC) return;
    int l = idx & (LTOK-1);
    int c = (idx >> 10) & (CC-1);
    int n = idx >> 18;
    o[idx] = x[((size_t)n*LTOK + l)*CC + c];
}

// ---------------- PRoPE matrix build ----------------
__device__ __forceinline__ void prope_forward(const float* vm, const float* Kc,
                                              float u, float vyy, float* M) {
    float fx = Kc[0] * (1.0f/128.0f), fy = Kc[4] * (1.0f/128.0f);
    float cx = Kc[2] * (1.0f/128.0f), cy = Kc[5] * (1.0f/128.0f);
    float a = cx - u, b = cy - vyy;
    #pragma unroll
    for (int c = 0; c < 4; c++) {
        M[0*4+c] = fx*vm[0*4+c] + a*vm[2*4+c];
        M[1*4+c] = fy*vm[1*4+c] + b*vm[2*4+c];
        M[2*4+c] = vm[2*4+c];
        M[3*4+c] = vm[3*4+c];
    }
}

__global__ void k_prope_q(const float* __restrict__ vms, const float* __restrict__ Ks,
                          float* __restrict__ Mq, float* __restrict__ Mqi) {
    int idx = blockIdx.x * blockDim.x + threadIdx.x;
    if (idx >= NVB*LTOK) return;
    int n = idx >> 10, t = idx & (LTOK-1);
    int px = t & 31, py = t >> 5;
    float u  = (px + 0.5f) * (1.0f/32.0f);
    float vy = (py + 0.5f) * (1.0f/32.0f);
    const float* vm = vms + n*16;
    const float* Kc = Ks + n*9;
    float M[16];
    prope_forward(vm, Kc, u, vy, M);
    #pragma unroll
    for (int i = 0; i < 16; i++) Mq[idx*16+i] = M[i];

    float r00=vm[0],r01=vm[1],r02=vm[2],  t0=vm[3];
    float r10=vm[4],r11=vm[5],r12=vm[6],  t1=vm[7];
    float r20=vm[8],r21=vm[9],r22=vm[10], t2=vm[11];
    float det = r00*(r11*r22-r12*r21) - r01*(r10*r22-r12*r20) + r02*(r10*r21-r11*r20);
    float id = 1.0f/det;
    float Ri[9];
    Ri[0]=(r11*r22-r12*r21)*id; Ri[1]=(r02*r21-r01*r22)*id; Ri[2]=(r01*r12-r02*r11)*id;
    Ri[3]=(r12*r20-r10*r22)*id; Ri[4]=(r00*r22-r02*r20)*id; Ri[5]=(r02*r10-r00*r12)*id;
    Ri[6]=(r10*r21-r11*r20)*id; Ri[7]=(r01*r20-r00*r21)*id; Ri[8]=(r00*r11-r01*r10)*id;
    float ti0 = -(Ri[0]*t0 + Ri[1]*t1 + Ri[2]*t2);
    float ti1 = -(Ri[3]*t0 + Ri[4]*t1 + Ri[5]*t2);
    float ti2 = -(Ri[6]*t0 + Ri[7]*t1 + Ri[8]*t2);
    float fx = Kc[0]*(1.0f/128.0f), fy = Kc[4]*(1.0f/128.0f);
    float cx = Kc[2]*(1.0f/128.0f), cy = Kc[5]*(1.0f/128.0f);
    float a = cx - u, b = cy - vy;
    float ifx = 1.0f/fx, ify = 1.0f/fy;
    float Mi[16];
    float tv[3] = {ti0, ti1, ti2};
    #pragma unroll
    for (int i = 0; i < 3; i++) {
        Mi[i*4+0] = Ri[i*3+0]*ifx;
        Mi[i*4+1] = Ri[i*3+1]*ify;
        Mi[i*4+2] = -Ri[i*3+0]*a*ifx - Ri[i*3+1]*b*ify + Ri[i*3+2];
        Mi[i*4+3] = tv[i];
    }
    Mi[12]=0.f; Mi[13]=0.f; Mi[14]=0.f; Mi[15]=1.f;
    #pragma unroll
    for (int i = 0; i < 16; i++) Mqi[idx*16+i] = Mi[i];
}

// ---------------- per-token applies: Q + per-camera K/V ----------
__global__ void k_apply_all(const float* __restrict__ qkv, int stride,
                            const float* __restrict__ Mqi, const float* __restrict__ Mq,
                            uint32_t* __restrict__ qph, uint32_t* __restrict__ qpl,
                            uint32_t* __restrict__ kph, uint32_t* __restrict__ kpl,
                            uint32_t* __restrict__ vph, uint32_t* __restrict__ vpl)
{
    int idx = blockIdx.x * blockDim.x + threadIdx.x;
    if (idx < NAPP) {
        int g = idx & 15, h = (idx >> 4) & 3, t = (idx >> 6) & (LTOK-1), n = idx >> 16;
        const float* M = Mqi + ((size_t)(n*LTOK + t))*16;
        const float* s = qkv + ((size_t)(n*LTOK + t))*stride + h*HD + g*4;
        float x0=s[0], x1=s[1], x2=s[2], x3=s[3];
        float d[4];
        #pragma unroll
        for (int i = 0; i < 4; i++)
            d[i] = M[0*4+i]*x0 + M[1*4+i]*x1 + M[2*4+i]*x2 + M[3*4+i]*x3;
        uint32_t h0, l0, h1, l1;
        cvt_hl(d[0]*0.125f, d[1]*0.125f, h0, l0);
        cvt_hl(d[2]*0.125f, d[3]*0.125f, h1, l1);
        size_t wb = (((size_t)(n*NH + h))*LTOK + t)*32 + g*2;
        qph[wb] = h0;   qpl[wb] = l0;
        qph[wb+1] = h1; qpl[wb+1] = l1;
    } else if (idx < 2*NAPP) {
        int i2 = idx - NAPP;
        int g = i2 & 15, h = (i2 >> 4) & 3, t = (i2 >> 6) & (LTOK-1), n = i2 >> 16;
        const float* M = Mq + ((size_t)(n*LTOK + t))*16;
        const float* s = qkv + ((size_t)(n*LTOK + t))*stride + 256 + h*HD + g*4;
        float x0=s[0], x1=s[1], x2=s[2], x3=s[3];
        float d[4];
        #pragma unroll
        for (int i = 0; i < 4; i++)
            d[i] = M[i*4+0]*x0 + M[i*4+1]*x1 + M[i*4+2]*x2 + M[i*4+3]*x3;
        size_t wb = (((size_t)(n*NH + h))*LTOK + t)*32 + g*2;
        uint32_t h0, l0, h1, l1;
        cvt_hl(d[0], d[1], h0, l0);
        cvt_hl(d[2], d[3], h1, l1);
        kph[wb] = h0;   kpl[wb] = l0;
        kph[wb+1] = h1; kpl[wb+1] = l1;
    } else if (idx < 3*NAPP) {
        int i2 = idx - 2*NAPP;
        int tt = i2 & (LTOK-1);
        int rest = i2 >> 10;
        int g = rest & 15, h = (rest >> 4) & 3, n = rest >> 6;
        const float* M = Mq + ((size_t)(n*LTOK + tt))*16;
        const float* s = qkv + ((size_t)(n*LTOK + tt))*stride + 512 + h*HD + g*4;
        float x0=s[0], x1=s[1], x2=s[2], x3=s[3];
        #pragma unroll
        for (int i = 0; i < 4; i++) {
            float v = M[i*4+0]*x0 + M[i*4+1]*x1 + M[i*4+2]*x2 + M[i*4+3]*x3;
            float vn = __shfl_down_sync(0xffffffff, v, 1);
            if ((tt & 1) == 0) {
                uint32_t hh2, ll2;
                cvt_hl(v, vn, hh2, ll2);
                size_t wb = ((size_t)(n*NH + h)*HD + g*4 + i)*(LTOK >> 1) + (tt >> 1);
                vph[wb] = hh2; vpl[wb] = ll2;
            }
        }
    }
}

// ---------------- layernorm ----------------
__global__ void k_ln(float* __restrict__ dst, const float* __restrict__ parts, int nparts,
                     const float* __restrict__ w, const float* __restrict__ b, int add,
                     uint32_t* __restrict__ oh, uint32_t* __restrict__ ol,
                     uint32_t* __restrict__ oh2, uint32_t* __restrict__ ol2,
                     uint32_t* __restrict__ ch, uint32_t* __restrict__ cl, int catHalf) {
    __shared__ float red[256];
    int row = blockIdx.x, tid = threadIdx.x;
    float v = parts[(size_t)row*CC + tid];
    for (int p = 1; p < nparts; p++)
        v += parts[(size_t)p*ROWS_*CC + (size_t)row*CC + tid];
    red[tid] = v; __syncthreads();
    for (int s = 128; s > 0; s >>= 1) { if (tid < s) red[tid] += red[tid+s]; __syncthreads(); }
    float mu = red[0] * (1.0f/CC); __syncthreads();
    float d = v - mu;
    red[tid] = d * d; __syncthreads();
    for (int s = 128; s > 0; s >>= 1) { if (tid < s) red[tid] += red[tid+s]; __syncthreads(); }
    float var = red[0] * (1.0f/CC);
    float o = d * rsqrtf(var + 1e-5f) * w[tid] + b[tid];
    float fin;
    if (add) { fin = dst[(size_t)row*CC + tid] + o; dst[(size_t)row*CC + tid] = fin; }
    else     { fin = o; dst[(size_t)row*CC + tid] = fin; }
    if (oh || ch) {
        __syncthreads();
        red[tid] = fin;
        __syncthreads();
        if (tid < 128) {
            uint32_t h, l;
            cvt_hl(red[2*tid], red[2*tid+1], h, l);
            if (oh) {
                oh[(size_t)row*(CC/2) + tid] = h;
                ol[(size_t)row*(CC/2) + tid] = l;
                if (oh2) {
                    oh2[(size_t)row*(CC/2) + tid] = h;
                    ol2[(size_t)row*(CC/2) + tid] = l;
                }
            }
            if (ch) {
                size_t cw = (size_t)row*(FFNI/2) + catHalf*128 + tid;
                ch[cw] = h; cl[cw] = l;
            }
        }
    }
}

// ---------------- host driver ----------------
static const int GSMEM128 = 98304;
static const int GSMEM64  = 73728;

static void gemm128(const uint32_t* Ah, const uint32_t* Al,
                    const uint32_t* A2h, const uint32_t* A2l, int nsplit,
                    const uint32_t* Bh, const uint32_t* Bl,
                    float* C, int M, int N, int K) {
    dim3 g(N/128, M/128, 1);
    tc_gemm<128,0><<<g, 256, GSMEM128>>>(Ah, Al, A2h, A2l, nsplit, Bh, Bl,
                                         C, nullptr, nullptr, M, N, K, K);
}
static void gemm64s(const uint32_t* Ah, const uint32_t* Al,
                    const uint32_t* Bh, const uint32_t* Bl,
                    float* C, int M, int N, int Ktot, int nz) {
    dim3 g(N/64, M/128, nz);
    tc_gemm<64,0><<<g, 256, GSMEM64>>>(Ah, Al, Ah, Al, 1<<30, Bh, Bl,
                                       C, nullptr, nullptr, M, N, Ktot/nz, Ktot);
}
static void gemm_gelu_hl(const uint32_t* Ah, const uint32_t* Al,
                         const uint32_t* Bh, const uint32_t* Bl,
                         uint32_t* Oh, uint32_t* Ol, int M, int N, int K) {
    dim3 g(N/128, M/128, 1);
    tc_gemm<128,1><<<g, 256, GSMEM128>>>(Ah, Al, Ah, Al, 1<<30, Bh, Bl,
                                         nullptr, Oh, Ol, M, N, K, K);
}

extern "C" void kernel_launch(void* const* d_in, const int* in_sizes, int n_in,
                              void* d_out, int out_size) {
    const float* feats = (const float*)d_in[0];
    const float* vms   = (const float*)d_in[1];
    const float* Ks    = (const float*)d_in[2];
    const float* Wq    = (const float*)d_in[3];
    const float* Wk    = (const float*)d_in[4];
    const float* Wv    = (const float*)d_in[5];
    const float* Wm    = (const float*)d_in[6];
    const float* n1w   = (const float*)d_in[7];
    const float* n1b   = (const float*)d_in[8];
    const float* W1    = (const float*)d_in[9];
    const float* W2    = (const float*)d_in[10];
    const float* n2w   = (const float*)d_in[11];
    const float* n2b   = (const float*)d_in[12];

    cudaFuncSetAttribute(tc_gemm<128,0>, cudaFuncAttributeMaxDynamicSharedMemorySize, GSMEM128);
    cudaFuncSetAttribute(tc_gemm<128,1>, cudaFuncAttributeMaxDynamicSharedMemorySize, GSMEM128);
    cudaFuncSetAttribute(tc_gemm<64,0>,  cudaFuncAttributeMaxDynamicSharedMemorySize, GSMEM64);

    void* p;
    float *x,*qkv,*O,*msg,*msg2,*h22,*Mq,*Mqi;
    uint32_t *qph,*qpl,*kph,*kpl,*vph,*vpl;
    uint32_t *xh,*xl,*xpreh,*xprel,*omh,*oml,*cath,*catl,*hh,*hl,*wh,*wl;
    cudaGetSymbolAddress(&p, g_x);    x   = (float*)p;
    cudaGetSymbolAddress(&p, g_qkv);  qkv = (float*)p;
    cudaGetSymbolAddress(&p, g_qph);  qph = (uint32_t*)p;
    cudaGetSymbolAddress(&p, g_qpl);  qpl = (uint32_t*)p;
    cudaGetSymbolAddress(&p, g_kph);  kph = (uint32_t*)p;
    cudaGetSymbolAddress(&p, g_kpl);  kpl = (uint32_t*)p;
    cudaGetSymbolAddress(&p, g_vph);  vph = (uint32_t*)p;
    cudaGetSymbolAddress(&p, g_vpl);  vpl = (uint32_t*)p;
    cudaGetSymbolAddress(&p, g_O);    O   = (float*)p;
    cudaGetSymbolAddress(&p, g_msg);  msg = (float*)p;
    cudaGetSymbolAddress(&p, g_msg2); msg2= (float*)p;
    cudaGetSymbolAddress(&p, g_h22);  h22 = (float*)p;
    cudaGetSymbolAddress(&p, g_Mq);   Mq  = (float*)p;
    cudaGetSymbolAddress(&p, g_Mqi);  Mqi = (float*)p;
    cudaGetSymbolAddress(&p, g_xh);    xh    = (uint32_t*)p;
    cudaGetSymbolAddress(&p, g_xl);    xl    = (uint32_t*)p;
    cudaGetSymbolAddress(&p, g_xpreh); xpreh = (uint32_t*)p;
    cudaGetSymbolAddress(&p, g_xprel); xprel = (uint32_t*)p;
    cudaGetSymbolAddress(&p, g_omh);   omh   = (uint32_t*)p;
    cudaGetSymbolAddress(&p, g_oml);   oml   = (uint32_t*)p;
    cudaGetSymbolAddress(&p, g_cath);  cath  = (uint32_t*)p;
    cudaGetSymbolAddress(&p, g_catl);  catl  = (uint32_t*)p;
    cudaGetSymbolAddress(&p, g_hh);    hh    = (uint32_t*)p;
    cudaGetSymbolAddress(&p, g_hl);    hl    = (uint32_t*)p;
    cudaGetSymbolAddress(&p, g_wh);    wh    = (uint32_t*)p;
    cudaGetSymbolAddress(&p, g_wl);    wl    = (uint32_t*)p;

    const int ROWS = ROWS_;
    const int NEL  = ROWS * CC;

    k_cvt_all<<<WTOT/256, 256>>>(Wq, Wk, Wv, Wm, W1, W2, wh, wl);
    k_build_x<<<(XW+255)/256, 256>>>(feats, x, xh, xl, xpreh, xprel);
    k_prope_q<<<(NVB*LTOK+255)/256, 256>>>(vms, Ks, Mq, Mqi);

    for (int ly = 0; ly < 2; ly++) {
        // ---------- self attention ----------
        gemm128(xh, xl, xh, xl, 1<<30,
                wh + WQKV0 + (ly*2+0)*98304, wl + WQKV0 + (ly*2+0)*98304,
                qkv, ROWS, 768, CC);
        k_apply_all<<<(3*NAPP)/256, 256>>>(qkv, 768, Mqi, Mq,
                                           qph, qpl, kph, kpl, vph, vpl);
        k_flash<<<dim3(LTOK/128, NVB*NH), 256>>>(qph, qpl, kph, kpl, vph, vpl, O, LTOK);
        k_apply_out<<<NAPP/256, 256>>>(O, Mqi, omh, oml);
        gemm64s(omh, oml, wh + WMO + (ly*2+0)*32768, wl + WMO + (ly*2+0)*32768,
                msg2, ROWS, CC, CC, 2);
        k_ln<<<ROWS, 256>>>(x, msg2, 2, n1w + (ly*2+0)*CC, n1b + (ly*2+0)*CC, 1,
                            xh, xl, nullptr, nullptr, cath, catl, 0);

        // ---------- cross attention (per-camera K/V, dedup) ----------
        gemm128(xh, xl, xpreh, xprel, 256,
                wh + WQKV0 + (ly*2+1)*98304, wl + WQKV0 + (ly*2+1)*98304,
                qkv, ROWS, 768, CC);
        k_apply_all<<<(3*NAPP)/256, 256>>>(qkv, 768, Mqi, Mq,
                                           qph, qpl, kph, kpl, vph, vpl);
        k_flash<<<dim3(LTOK/128, NVB*NH), 256>>>(qph, qpl, kph, kpl, vph, vpl, O, TKX);
        k_apply_out<<<NAPP/256, 256>>>(O, Mqi, omh, oml);
        gemm64s(omh, oml, wh + WMO + (ly*2+1)*32768, wl + WMO + (ly*2+1)*32768,
                msg2, ROWS, CC, CC, 2);
        k_ln<<<ROWS, 256>>>(msg, msg2, 2, n1w + (ly*2+1)*CC, n1b + (ly*2+1)*CC, 0,
                            nullptr, nullptr, nullptr, nullptr, cath, catl, 1);

        // ---------- FFN ----------
        gemm_gelu_hl(cath, catl,
                     wh + W1O + (size_t)ly*524288, wl + W1O + (size_t)ly*524288,
                     hh, hl, ROWS, FFNH, FFNI);
        gemm64s(hh, hl, wh + W2O + (size_t)ly*262144, wl + W2O + (size_t)ly*262144,
                h22, ROWS, CC, FFNH, 4);
        k_ln<<<ROWS, 256>>>(x, h22, 4, n2w + ly*CC, n2b + ly*CC, 1,
                            xh, xl, xpreh, xprel, nullptr, nullptr, 0);
    }

    k_final<<<(NEL+255)/256, 256>>>(x, (float*)d_out);
}